// round 10
// baseline (speedup 1.0000x reference)
#include <cuda_runtime.h>
#include <cuda_fp16.h>
#include <math.h>
#include <stdint.h>

// ---------------- problem constants ----------------
#define BB   4
#define TT   4096
#define BT   (BB*TT)      // 16384 tokens
#define HID  2048
#define ED   256          // engram dim
#define NH   8            // total hash heads
#define HD   32           // head dim
#define KW   4            // conv kernel
#define DILN 3            // dilation
#define PADL 9            // causal left pad

// ---------------- scratch (device globals; no allocation) ----------------
__device__ __align__(16) __half gEh [(size_t)BT * ED];      // e' fp16 (8 MB)
__device__ __align__(16) __half gMh [(size_t)HID * ED];     // M = Wo@Wv fp16 (1 MB)
__device__ __align__(16) __half gWkh[(size_t)HID * ED];     // Wk fp16 (1 MB)
__device__ float gG[BT];                                    // per-token gate
__device__ __align__(16) float gPart[(size_t)BT * 16 * 16]; // partials / matM split-K scratch

// ---------------- helpers ----------------------------------------------
__device__ __forceinline__ uint32_t f2tf32(float f) {
    uint32_t u; asm("cvt.rna.tf32.f32 %0, %1;" : "=r"(u) : "f"(f)); return u;
}
__device__ __forceinline__ uint32_t smem_u32(const void* p) {
    uint32_t r;
    asm("{ .reg .u64 t; cvta.to.shared.u64 t, %1; cvt.u32.u64 %0, t; }" : "=r"(r) : "l"(p));
    return r;
}
__device__ __forceinline__ void ldsm4(uint32_t& r0, uint32_t& r1, uint32_t& r2, uint32_t& r3,
                                      uint32_t addr) {
    asm volatile("ldmatrix.sync.aligned.m8n8.x4.shared.b16 {%0,%1,%2,%3}, [%4];"
                 : "=r"(r0), "=r"(r1), "=r"(r2), "=r"(r3) : "r"(addr));
}
__device__ __forceinline__ void mma_f16(float* c, const uint32_t* a, uint32_t b0, uint32_t b1) {
    asm volatile("mma.sync.aligned.m16n8k16.row.col.f32.f16.f16.f32 "
                 "{%0,%1,%2,%3}, {%4,%5,%6,%7}, {%8,%9}, {%0,%1,%2,%3};"
                 : "+f"(c[0]), "+f"(c[1]), "+f"(c[2]), "+f"(c[3])
                 : "r"(a[0]), "r"(a[1]), "r"(a[2]), "r"(a[3]), "r"(b0), "r"(b1));
}
__device__ __forceinline__ void mma_tf32(float* c, const uint32_t* a, uint32_t b0, uint32_t b1) {
    asm volatile("mma.sync.aligned.m16n8k8.row.col.f32.tf32.tf32.f32 "
                 "{%0,%1,%2,%3}, {%4,%5,%6,%7}, {%8,%9}, {%0,%1,%2,%3};"
                 : "+f"(c[0]), "+f"(c[1]), "+f"(c[2]), "+f"(c[3])
                 : "r"(a[0]), "r"(a[1]), "r"(a[2]), "r"(a[3]), "r"(b0), "r"(b1));
}
__device__ __forceinline__ void cpa16(uint32_t dst, const void* src) {
    asm volatile("cp.async.ca.shared.global [%0], [%1], 16;" :: "r"(dst), "l"(src));
}
__device__ __forceinline__ void cpa_commit() { asm volatile("cp.async.commit_group;"); }
template <int N> __device__ __forceinline__ void cpa_wait() {
    asm volatile("cp.async.wait_group %0;" :: "n"(N) : "memory");
}

// =====================================================================
// Kernel 0: matM split-K  (tf32 tensor cores)  -- unchanged from R9
// =====================================================================
#define MLDS 36
__global__ __launch_bounds__(256) void k_matM5(const float* __restrict__ Wo,
                                               const float* __restrict__ Wv) {
    __shared__ uint32_t As[128 * MLDS];
    __shared__ uint32_t Bs[64 * MLDS];
    int bn = blockIdx.x * 64;
    int bm = blockIdx.y * 128;
    int K0 = blockIdx.z * 512;
    int tid = threadIdx.x, lane = tid & 31, wid = tid >> 5;
    int wm = wid & 3, wn = wid >> 2;

    float acc[2][4][4];
#pragma unroll
    for (int mt = 0; mt < 2; mt++)
#pragma unroll
        for (int nt = 0; nt < 4; nt++)
#pragma unroll
            for (int r = 0; r < 4; r++) acc[mt][nt][r] = 0.f;

    uint32_t as0 = smem_u32(As), bs0 = smem_u32(Bs);
    uint32_t a_base = as0 + (((wm * 32 + (lane & 15)) * MLDS + (lane >> 4) * 4) << 2);
    uint32_t b_base = bs0 + (((wn * 32 + (lane >> 4) * 8 + (lane & 7)) * MLDS
                              + ((lane >> 3) & 1) * 4) << 2);

    for (int kt = 0; kt < 512; kt += 32) {
#pragma unroll
        for (int i = 0; i < 4; i++) {
            int idx = tid + 256 * i;
            int r = idx >> 3, q = idx & 7;
            float4 v = *(const float4*)(Wo + (size_t)(bm + r) * 2048 + K0 + kt + q * 4);
            uint32_t* d = &As[r * MLDS + q * 4];
            d[0] = f2tf32(v.x); d[1] = f2tf32(v.y); d[2] = f2tf32(v.z); d[3] = f2tf32(v.w);
        }
#pragma unroll
        for (int p = 0; p < 2; p++) {
            int kk = (tid >> 4) + p * 16;
            int c4 = (tid & 15) * 4;
            float4 v = *(const float4*)(Wv + (size_t)(K0 + kt + kk) * 256 + bn + c4);
            Bs[(c4 + 0) * MLDS + kk] = f2tf32(v.x);
            Bs[(c4 + 1) * MLDS + kk] = f2tf32(v.y);
            Bs[(c4 + 2) * MLDS + kk] = f2tf32(v.z);
            Bs[(c4 + 3) * MLDS + kk] = f2tf32(v.w);
        }
        __syncthreads();
#pragma unroll
        for (int ks = 0; ks < 4; ks++) {
            uint32_t a[2][4], b[2][4];
#pragma unroll
            for (int mt = 0; mt < 2; mt++)
                ldsm4(a[mt][0], a[mt][1], a[mt][2], a[mt][3],
                      a_base + ((mt * 16 * MLDS + ks * 8) << 2));
#pragma unroll
            for (int p = 0; p < 2; p++)
                ldsm4(b[p][0], b[p][1], b[p][2], b[p][3],
                      b_base + ((p * 16 * MLDS + ks * 8) << 2));
#pragma unroll
            for (int mt = 0; mt < 2; mt++)
#pragma unroll
                for (int nt = 0; nt < 4; nt++) {
                    int p = nt >> 1, s = (nt & 1) * 2;
                    mma_tf32(acc[mt][nt], a[mt], b[p][s], b[p][s + 1]);
                }
        }
        __syncthreads();
    }

    float* pm = gPart + (size_t)blockIdx.z * (2048 * 256);
#pragma unroll
    for (int mt = 0; mt < 2; mt++) {
        int r0 = bm + wm * 32 + mt * 16 + (lane >> 2);
#pragma unroll
        for (int nt = 0; nt < 4; nt++) {
            int c0 = bn + wn * 32 + nt * 8 + (lane & 3) * 2;
            *(float2*)(pm + (size_t)r0 * 256 + c0) =
                make_float2(acc[mt][nt][0], acc[mt][nt][1]);
            *(float2*)(pm + (size_t)(r0 + 8) * 256 + c0) =
                make_float2(acc[mt][nt][2], acc[mt][nt][3]);
        }
    }
}

__global__ __launch_bounds__(256) void k_matred() {
    int i = (blockIdx.x * 256 + threadIdx.x) * 4;
    float4 s = *(const float4*)(gPart + i);
#pragma unroll
    for (int kc = 1; kc < 4; kc++) {
        float4 v = *(const float4*)(gPart + (size_t)kc * (2048 * 256) + i);
        s.x += v.x; s.y += v.y; s.z += v.z; s.w += v.w;
    }
    *(__half2*)(gMh + i)     = __floats2half2_rn(s.x, s.y);
    *(__half2*)(gMh + i + 2) = __floats2half2_rn(s.z, s.w);
}

__global__ __launch_bounds__(256) void k_cvtWk(const float* __restrict__ Wk) {
    int i = (blockIdx.x * 256 + threadIdx.x) * 4;
    float4 v = *(const float4*)(Wk + i);
    *(__half2*)(gWkh + i)     = __floats2half2_rn(v.x, v.y);
    *(__half2*)(gWkh + i + 2) = __floats2half2_rn(v.z, v.w);
}

// =====================================================================
// Kernel 1: hash-gather + dilated causal depthwise conv + LN + SiLU -> gEh
// =====================================================================
__global__ __launch_bounds__(256) void k_embed(const int* __restrict__ hashes,
                                               const int* __restrict__ offs,
                                               const float* __restrict__ emb,
                                               const float* __restrict__ cw,
                                               const float* __restrict__ lg,
                                               const float* __restrict__ lb) {
    const int TB = 32, HALO = PADL;
    __shared__ float se[(TB + HALO) * ED];
    __shared__ float swt[KW * ED];
    __shared__ float sg[ED], sb[ED];

    int tid = threadIdx.x;
    int b = blockIdx.y, t0 = blockIdx.x * TB;

    sg[tid] = lg[tid];
    sb[tid] = lb[tid];
#pragma unroll
    for (int k = 0; k < KW; k++) swt[k * ED + tid] = cw[tid * KW + k];

    int h = tid >> 5, d = tid & 31;
    int off_h = offs[h];
    for (int lt = 0; lt < TB + HALO; lt++) {
        int t = t0 - HALO + lt;
        float v = 0.f;
        if (t >= 0) {
            int row = hashes[(b * TT + t) * NH + h] + off_h;
            v = emb[(size_t)row * HD + d];
        }
        se[lt * ED + tid] = v;
    }
    __syncthreads();

    int wid = tid >> 5, lane = tid & 31;
    for (int it = 0; it < TB / 8; it++) {
        int tok = it * 8 + wid;
        int lt = tok + HALO;
        float c[8], ev[8];
        float s = 0.f, q = 0.f;
#pragma unroll
        for (int j = 0; j < 8; j++) {
            int ch = lane + 32 * j;
            float a = 0.f;
#pragma unroll
            for (int k = 0; k < KW; k++)
                a += se[(lt - PADL + k * DILN) * ED + ch] * swt[k * ED + ch];
            c[j] = a;
            ev[j] = se[lt * ED + ch];
            s += a; q += a * a;
        }
#pragma unroll
        for (int o = 16; o; o >>= 1) {
            s += __shfl_xor_sync(0xffffffffu, s, o);
            q += __shfl_xor_sync(0xffffffffu, q, o);
        }
        float mean = s * (1.f / ED);
        float var  = q * (1.f / ED) - mean * mean;
        float rstd = rsqrtf(var + 1e-5f);
#pragma unroll
        for (int j = 0; j < 8; j++) {
            int ch = lane + 32 * j;
            float y = (c[j] - mean) * rstd * sg[ch] + sb[ch];
            float o = ev[j] + y * (1.f / (1.f + expf(-y)));
            gEh[(size_t)(b * TT + t0 + tok) * ED + ch] = __float2half_rn(o);
        }
    }
}

// =====================================================================
// Kernel 3/5: fp16 tensor GEMM NT, 128x256 block, 64x64 warp tiles.
//   C[BT x 2048] = gEh[BT x 256] @ B[2048 x 256]^T
//   MODE 0: B = gWkh; epilogue -> 9 raw gate partials. MODE 1: B = gMh, scaled store.
//   8 warps (2m x 4n); BK=64 halfs; 2-stage cp.async; smem 110592 B.
// =====================================================================
#define LDSH 72
#define ABUF (128 * LDSH)                // halfs per A stage
#define BBUF (256 * LDSH)                // halfs per B stage
#define GSM  ((ABUF + BBUF) * 2 * 2)     // bytes: 2 stages

template <int MODE>
__global__ __launch_bounds__(256, 1) void k_gemm(float* __restrict__ Cout,
                                                 const float* __restrict__ x,
                                                 const float* __restrict__ lkg,
                                                 const float* __restrict__ lkb,
                                                 const float* __restrict__ lqg,
                                                 const float* __restrict__ lqb) {
    extern __shared__ __half sh[];
    __half* As = sh;                     // [2][ABUF]
    __half* Bs = sh + 2 * ABUF;          // [2][BBUF]

    const __half* A  = gEh;
    const __half* Bp = (MODE == 0) ? gWkh : gMh;

    int bm = blockIdx.y * 128, bn = blockIdx.x * 256;
    int tid = threadIdx.x, lane = tid & 31, wid = tid >> 5;
    int wm = wid & 1, wn = wid >> 1;     // 2m x 4n, warp tile 64x64

    float acc[4][8][4];
#pragma unroll
    for (int mt = 0; mt < 4; mt++)
#pragma unroll
        for (int nt = 0; nt < 8; nt++)
#pragma unroll
            for (int r = 0; r < 4; r++) acc[mt][nt][r] = 0.f;

    uint32_t as0 = smem_u32(As), bs0 = smem_u32(Bs);
    uint32_t a_base = as0 + (((wm * 64 + (lane & 15)) * LDSH + (lane >> 4) * 8) << 1);
    uint32_t b_base = bs0 + (((wn * 64 + (lane >> 4) * 8 + (lane & 7)) * LDSH
                              + ((lane >> 3) & 1) * 8) << 1);

    auto issue = [&](int t) {
        int s = t & 1;
        uint32_t ao = as0 + s * (ABUF * 2);
        uint32_t bo = bs0 + s * (BBUF * 2);
        int kt = t * 64;
#pragma unroll
        for (int i = 0; i < 4; i++) {    // A: 1024 x 16B
            int idx = tid + 256 * i;
            int row = idx >> 3, q = idx & 7;
            cpa16(ao + ((row * LDSH + q * 8) << 1), A + (size_t)(bm + row) * ED + kt + q * 8);
        }
#pragma unroll
        for (int i = 0; i < 8; i++) {    // B: 2048 x 16B
            int idx = tid + 256 * i;
            int row = idx >> 3, q = idx & 7;
            cpa16(bo + ((row * LDSH + q * 8) << 1), Bp + (size_t)(bn + row) * ED + kt + q * 8);
        }
        cpa_commit();
    };

    issue(0);
    for (int t = 0; t < 4; t++) {        // K = 256 / 64
        int s = t & 1;
        if (t < 3) { issue(t + 1); cpa_wait<1>(); }
        else       { cpa_wait<0>(); }
        __syncthreads();
        uint32_t abuf = a_base + s * (ABUF * 2);
        uint32_t bbuf = b_base + s * (BBUF * 2);
#pragma unroll
        for (int ks = 0; ks < 4; ks++) { // 4 x k16
            uint32_t a[4][4], b[4][4];
#pragma unroll
            for (int mt = 0; mt < 4; mt++)
                ldsm4(a[mt][0], a[mt][1], a[mt][2], a[mt][3],
                      abuf + ((mt * 16 * LDSH + ks * 16) << 1));
#pragma unroll
            for (int p = 0; p < 4; p++)
                ldsm4(b[p][0], b[p][1], b[p][2], b[p][3],
                      bbuf + ((p * 16 * LDSH + ks * 16) << 1));
#pragma unroll
            for (int mt = 0; mt < 4; mt++)
#pragma unroll
                for (int nt = 0; nt < 8; nt++) {
                    int p = nt >> 1, q = (nt & 1) * 2;
                    mma_f16(acc[mt][nt], a[mt], b[p][q], b[p][q + 1]);
                }
        }
        __syncthreads();
    }

    if (MODE == 1) {
#pragma unroll
        for (int mt = 0; mt < 4; mt++) {
            int r0 = bm + wm * 64 + mt * 16 + (lane >> 2);
            float s0 = gG[r0], s1 = gG[r0 + 8];
#pragma unroll
            for (int nt = 0; nt < 8; nt++) {
                int c0 = bn + wn * 64 + nt * 8 + (lane & 3) * 2;
                *(float2*)(Cout + (size_t)r0 * HID + c0) =
                    make_float2(acc[mt][nt][0] * s0, acc[mt][nt][1] * s0);
                *(float2*)(Cout + (size_t)(r0 + 8) * HID + c0) =
                    make_float2(acc[mt][nt][2] * s1, acc[mt][nt][3] * s1);
            }
        }
    } else {
        // 9 raw partials: P0=Σkp·a·x P1=Σkp·a P2=Σa·x P3=Σkp·b P4=Σc·x
        //                 P5=Σkp P6=Σkp² P7=Σx P8=Σx²  (a=lkg·lqg, b=lkg·lqb, c=lkb·lqg)
        float* sA   = (float*)sh;        // [256] per-col a
        float* sB   = sA + 256;          // [256]
        float* sC   = sB + 256;          // [256]
        float* sRed = sC + 256;          // [4][128][9]
        {
            int col = bn + tid;
            float g1 = lkg[col], q1 = lqg[col], b1 = lkb[col], q0 = lqb[col];
            sA[tid] = g1 * q1; sB[tid] = g1 * q0; sC[tid] = b1 * q1;
        }
        __syncthreads();
#pragma unroll
        for (int mt = 0; mt < 4; mt++) {
#pragma unroll
            for (int half = 0; half < 2; half++) {
                int rl = wm * 64 + mt * 16 + half * 8 + (lane >> 2);
                int row = bm + rl;
                float p[9];
#pragma unroll
                for (int j = 0; j < 9; j++) p[j] = 0.f;
#pragma unroll
                for (int nt = 0; nt < 8; nt++) {
#pragma unroll
                    for (int e = 0; e < 2; e++) {
                        int cl = wn * 64 + nt * 8 + (lane & 3) * 2 + e;
                        float kp = acc[mt][nt][half * 2 + e];
                        float xv = x[(size_t)row * HID + bn + cl];
                        float a = sA[cl], b = sB[cl], c = sC[cl];
                        float ax = a * xv;
                        p[0] += kp * ax;
                        p[1] += kp * a;
                        p[2] += ax;
                        p[3] += kp * b;
                        p[4] += c * xv;
                        p[5] += kp;
                        p[6] += kp * kp;
                        p[7] += xv;
                        p[8] += xv * xv;
                    }
                }
#pragma unroll
                for (int o = 1; o <= 2; o <<= 1)
#pragma unroll
                    for (int j = 0; j < 9; j++)
                        p[j] += __shfl_xor_sync(0xffffffffu, p[j], o);
                if ((lane & 3) == 0) {
                    float* d = sRed + ((size_t)wn * 128 + rl) * 9;
#pragma unroll
                    for (int j = 0; j < 9; j++) d[j] = p[j];
                }
            }
        }
        __syncthreads();
        for (int idx = tid; idx < 128 * 9; idx += 256) {
            int rl = idx / 9, j = idx - rl * 9;
            float s = sRed[((size_t)0 * 128 + rl) * 9 + j]
                    + sRed[((size_t)1 * 128 + rl) * 9 + j]
                    + sRed[((size_t)2 * 128 + rl) * 9 + j]
                    + sRed[((size_t)3 * 128 + rl) * 9 + j];
            gPart[(((size_t)(bm + rl)) * 8 + blockIdx.x) * 16 + j] = s;
        }
    }
}

// =====================================================================
// Kernel 4: finalize gate (constants computed per-block; k_const deleted)
// =====================================================================
__global__ __launch_bounds__(256) void k_gfin(const float* __restrict__ lkg,
                                              const float* __restrict__ lkb,
                                              const float* __restrict__ lqg,
                                              const float* __restrict__ lqb) {
    __shared__ float cred[4][8];
    __shared__ float4 Cs;
    int tid = threadIdx.x, lane = tid & 31, wid = tid >> 5;

    float sa = 0.f, sb = 0.f, sc = 0.f, sd = 0.f;
    for (int c = tid; c < HID; c += 256) {
        float g1 = lkg[c], b1 = lkb[c], q1 = lqg[c], q0 = lqb[c];
        sa += g1 * q1; sb += g1 * q0; sc += b1 * q1; sd += b1 * q0;
    }
#pragma unroll
    for (int o = 16; o; o >>= 1) {
        sa += __shfl_xor_sync(0xffffffffu, sa, o);
        sb += __shfl_xor_sync(0xffffffffu, sb, o);
        sc += __shfl_xor_sync(0xffffffffu, sc, o);
        sd += __shfl_xor_sync(0xffffffffu, sd, o);
    }
    if (lane == 0) { cred[0][wid] = sa; cred[1][wid] = sb; cred[2][wid] = sc; cred[3][wid] = sd; }
    __syncthreads();
    if (tid == 0) {
        float a = 0.f, b = 0.f, c = 0.f, d = 0.f;
#pragma unroll
        for (int w = 0; w < 8; w++) { a += cred[0][w]; b += cred[1][w]; c += cred[2][w]; d += cred[3][w]; }
        Cs = make_float4(a, b, c, d);
    }
    __syncthreads();
    float4 C = Cs;

    int row = blockIdx.x * 256 + tid;
    float P[9];
#pragma unroll
    for (int j = 0; j < 9; j++) P[j] = 0.f;
#pragma unroll
    for (int nb = 0; nb < 8; nb++) {
        const float* p = gPart + (((size_t)row) * 8 + nb) * 16;
#pragma unroll
        for (int j = 0; j < 9; j++) P[j] += p[j];
    }
    float mk = P[5] * (1.f / HID);
    float rk = rsqrtf(P[6] * (1.f / HID) - mk * mk + 1e-5f);
    float mx = P[7] * (1.f / HID);
    float rx = rsqrtf(P[8] * (1.f / HID) - mx * mx + 1e-5f);
    float dot = rk * rx * (P[0] - mx * P[1] - mk * P[2] + mk * mx * C.x)
              + rk * (P[3] - mk * C.y)
              + rx * (P[4] - mx * C.z)
              + C.w;
    float s = dot * rsqrtf((float)HID);
    float a = fmaxf(fabsf(s), 1e-6f);
    float sgn = (s > 0.f) ? 1.f : ((s < 0.f) ? -1.f : 0.f);
    gG[row] = 1.f / (1.f + expf(-sqrtf(a) * sgn));
}

// =====================================================================
extern "C" void kernel_launch(void* const* d_in, const int* in_sizes, int n_in,
                              void* d_out, int out_size) {
    const float* x      = (const float*)d_in[0];
    const int*   hashes = (const int*)  d_in[1];
    const int*   offs   = (const int*)  d_in[2];
    const float* emb    = (const float*)d_in[3];
    const float* convw  = (const float*)d_in[4];
    const float* lncg   = (const float*)d_in[5];
    const float* lncb   = (const float*)d_in[6];
    const float* Wk     = (const float*)d_in[7];
    const float* Wv     = (const float*)d_in[8];
    const float* Wo     = (const float*)d_in[9];
    const float* lkg    = (const float*)d_in[10];
    const float* lkb    = (const float*)d_in[11];
    const float* lqg    = (const float*)d_in[12];
    const float* lqb    = (const float*)d_in[13];
    float* out = (float*)d_out;

    cudaFuncSetAttribute(k_gemm<0>, cudaFuncAttributeMaxDynamicSharedMemorySize, GSM);
    cudaFuncSetAttribute(k_gemm<1>, cudaFuncAttributeMaxDynamicSharedMemorySize, GSM);

    // 0) M = Wo @ Wv  (tf32 tensor cores, split-K=4) -> fp16 gMh;  Wk -> fp16
    k_matM5<<<dim3(4, 16, 4), 256>>>(Wo, Wv);
    k_matred<<<512, 256>>>();
    k_cvtWk<<<HID * ED / 1024, 256>>>(Wk);

    // 1) gather + conv + LN + SiLU -> gEh
    k_embed<<<dim3(TT / 32, BB), 256>>>(hashes, offs, emb, convw, lncg, lncb);

    // 2) KP GEMM (fp16, 128x256 tiles) with fused gate partials + x stats
    k_gemm<0><<<dim3(HID / 256, BT / 128), 256, GSM>>>(nullptr, x, lkg, lkb, lqg, lqb);

    // 3) finalize gate (constants inlined)
    k_gfin<<<BT / 256, 256>>>(lkg, lkb, lqg, lqb);

    // 4) out = diag(g) * (gEh @ M^T)
    k_gemm<1><<<dim3(HID / 256, BT / 128), 256, GSM>>>(out, x, lkg, lkb, lqg, lqb);
}

// round 12
// speedup vs baseline: 1.0237x; 1.0237x over previous
#include <cuda_runtime.h>
#include <cuda_fp16.h>
#include <math.h>
#include <stdint.h>

// ---------------- problem constants ----------------
#define BB   4
#define TT   4096
#define BT   (BB*TT)      // 16384 tokens
#define HID  2048
#define ED   256          // engram dim
#define NH   8            // total hash heads
#define HD   32           // head dim
#define KW   4            // conv kernel
#define DILN 3            // dilation
#define PADL 9            // causal left pad

// ---------------- scratch (device globals; no allocation) ----------------
__device__ __align__(16) __half gEh [(size_t)BT * ED];      // e' fp16 (8 MB)
__device__ __align__(16) __half gMh [(size_t)HID * ED];     // M = Wo@Wv fp16 (1 MB)
__device__ __align__(16) __half gWkh[(size_t)HID * ED];     // Wk fp16 (1 MB)
__device__ float gG[BT];                                    // per-token gate
__device__ __align__(16) float gPart[(size_t)BT * 16 * 16]; // partials / matM split-K scratch

// ---------------- helpers ----------------------------------------------
__device__ __forceinline__ uint32_t f2tf32(float f) {
    uint32_t u; asm("cvt.rna.tf32.f32 %0, %1;" : "=r"(u) : "f"(f)); return u;
}
__device__ __forceinline__ uint32_t smem_u32(const void* p) {
    uint32_t r;
    asm("{ .reg .u64 t; cvta.to.shared.u64 t, %1; cvt.u32.u64 %0, t; }" : "=r"(r) : "l"(p));
    return r;
}
__device__ __forceinline__ void ldsm4(uint32_t& r0, uint32_t& r1, uint32_t& r2, uint32_t& r3,
                                      uint32_t addr) {
    asm volatile("ldmatrix.sync.aligned.m8n8.x4.shared.b16 {%0,%1,%2,%3}, [%4];"
                 : "=r"(r0), "=r"(r1), "=r"(r2), "=r"(r3) : "r"(addr));
}
__device__ __forceinline__ void mma_f16(float* c, const uint32_t* a, uint32_t b0, uint32_t b1) {
    asm volatile("mma.sync.aligned.m16n8k16.row.col.f32.f16.f16.f32 "
                 "{%0,%1,%2,%3}, {%4,%5,%6,%7}, {%8,%9}, {%0,%1,%2,%3};"
                 : "+f"(c[0]), "+f"(c[1]), "+f"(c[2]), "+f"(c[3])
                 : "r"(a[0]), "r"(a[1]), "r"(a[2]), "r"(a[3]), "r"(b0), "r"(b1));
}
__device__ __forceinline__ void mma_tf32(float* c, const uint32_t* a, uint32_t b0, uint32_t b1) {
    asm volatile("mma.sync.aligned.m16n8k8.row.col.f32.tf32.tf32.f32 "
                 "{%0,%1,%2,%3}, {%4,%5,%6,%7}, {%8,%9}, {%0,%1,%2,%3};"
                 : "+f"(c[0]), "+f"(c[1]), "+f"(c[2]), "+f"(c[3])
                 : "r"(a[0]), "r"(a[1]), "r"(a[2]), "r"(a[3]), "r"(b0), "r"(b1));
}
__device__ __forceinline__ void cpa16(uint32_t dst, const void* src) {
    asm volatile("cp.async.ca.shared.global [%0], [%1], 16;" :: "r"(dst), "l"(src));
}
__device__ __forceinline__ void cpa_commit() { asm volatile("cp.async.commit_group;"); }
template <int N> __device__ __forceinline__ void cpa_wait() {
    asm volatile("cp.async.wait_group %0;" :: "n"(N) : "memory");
}

// =====================================================================
// Kernel 0: matM split-K (tf32 tensor cores)
// =====================================================================
#define MLDS 36
__global__ __launch_bounds__(256) void k_matM5(const float* __restrict__ Wo,
                                               const float* __restrict__ Wv) {
    __shared__ uint32_t As[128 * MLDS];
    __shared__ uint32_t Bs[64 * MLDS];
    int bn = blockIdx.x * 64;
    int bm = blockIdx.y * 128;
    int K0 = blockIdx.z * 512;
    int tid = threadIdx.x, lane = tid & 31, wid = tid >> 5;
    int wm = wid & 3, wn = wid >> 2;

    float acc[2][4][4];
#pragma unroll
    for (int mt = 0; mt < 2; mt++)
#pragma unroll
        for (int nt = 0; nt < 4; nt++)
#pragma unroll
            for (int r = 0; r < 4; r++) acc[mt][nt][r] = 0.f;

    uint32_t as0 = smem_u32(As), bs0 = smem_u32(Bs);
    uint32_t a_base = as0 + (((wm * 32 + (lane & 15)) * MLDS + (lane >> 4) * 4) << 2);
    uint32_t b_base = bs0 + (((wn * 32 + (lane >> 4) * 8 + (lane & 7)) * MLDS
                              + ((lane >> 3) & 1) * 4) << 2);

    for (int kt = 0; kt < 512; kt += 32) {
#pragma unroll
        for (int i = 0; i < 4; i++) {
            int idx = tid + 256 * i;
            int r = idx >> 3, q = idx & 7;
            float4 v = *(const float4*)(Wo + (size_t)(bm + r) * 2048 + K0 + kt + q * 4);
            uint32_t* d = &As[r * MLDS + q * 4];
            d[0] = f2tf32(v.x); d[1] = f2tf32(v.y); d[2] = f2tf32(v.z); d[3] = f2tf32(v.w);
        }
#pragma unroll
        for (int p = 0; p < 2; p++) {
            int kk = (tid >> 4) + p * 16;
            int c4 = (tid & 15) * 4;
            float4 v = *(const float4*)(Wv + (size_t)(K0 + kt + kk) * 256 + bn + c4);
            Bs[(c4 + 0) * MLDS + kk] = f2tf32(v.x);
            Bs[(c4 + 1) * MLDS + kk] = f2tf32(v.y);
            Bs[(c4 + 2) * MLDS + kk] = f2tf32(v.z);
            Bs[(c4 + 3) * MLDS + kk] = f2tf32(v.w);
        }
        __syncthreads();
#pragma unroll
        for (int ks = 0; ks < 4; ks++) {
            uint32_t a[2][4], b[2][4];
#pragma unroll
            for (int mt = 0; mt < 2; mt++)
                ldsm4(a[mt][0], a[mt][1], a[mt][2], a[mt][3],
                      a_base + ((mt * 16 * MLDS + ks * 8) << 2));
#pragma unroll
            for (int p = 0; p < 2; p++)
                ldsm4(b[p][0], b[p][1], b[p][2], b[p][3],
                      b_base + ((p * 16 * MLDS + ks * 8) << 2));
#pragma unroll
            for (int mt = 0; mt < 2; mt++)
#pragma unroll
                for (int nt = 0; nt < 4; nt++) {
                    int p = nt >> 1, s = (nt & 1) * 2;
                    mma_tf32(acc[mt][nt], a[mt], b[p][s], b[p][s + 1]);
                }
        }
        __syncthreads();
    }

    float* pm = gPart + (size_t)blockIdx.z * (2048 * 256);
#pragma unroll
    for (int mt = 0; mt < 2; mt++) {
        int r0 = bm + wm * 32 + mt * 16 + (lane >> 2);
#pragma unroll
        for (int nt = 0; nt < 4; nt++) {
            int c0 = bn + wn * 32 + nt * 8 + (lane & 3) * 2;
            *(float2*)(pm + (size_t)r0 * 256 + c0) =
                make_float2(acc[mt][nt][0], acc[mt][nt][1]);
            *(float2*)(pm + (size_t)(r0 + 8) * 256 + c0) =
                make_float2(acc[mt][nt][2], acc[mt][nt][3]);
        }
    }
}

__global__ __launch_bounds__(256) void k_matred() {
    int i = (blockIdx.x * 256 + threadIdx.x) * 4;
    float4 s = *(const float4*)(gPart + i);
#pragma unroll
    for (int kc = 1; kc < 4; kc++) {
        float4 v = *(const float4*)(gPart + (size_t)kc * (2048 * 256) + i);
        s.x += v.x; s.y += v.y; s.z += v.z; s.w += v.w;
    }
    *(__half2*)(gMh + i)     = __floats2half2_rn(s.x, s.y);
    *(__half2*)(gMh + i + 2) = __floats2half2_rn(s.z, s.w);
}

__global__ __launch_bounds__(256) void k_cvtWk(const float* __restrict__ Wk) {
    int i = (blockIdx.x * 256 + threadIdx.x) * 4;
    float4 v = *(const float4*)(Wk + i);
    *(__half2*)(gWkh + i)     = __floats2half2_rn(v.x, v.y);
    *(__half2*)(gWkh + i + 2) = __floats2half2_rn(v.z, v.w);
}

// =====================================================================
// Kernel 1: hash-gather + dilated causal depthwise conv + LN + SiLU -> gEh
//   se tile in DYNAMIC smem (41984 B) to stay under the 48 KB static cap.
//   Hashes staged to smem first so the emb gathers are independent LDGs.
// =====================================================================
#define TBEMB 32
#define ESM   ((TBEMB + PADL) * ED * 4)   // dynamic smem bytes = 41984

__global__ __launch_bounds__(256) void k_embed(const int* __restrict__ hashes,
                                               const int* __restrict__ offs,
                                               const float* __restrict__ emb,
                                               const float* __restrict__ cw,
                                               const float* __restrict__ lg,
                                               const float* __restrict__ lb) {
    const int TB = TBEMB, HALO = PADL;
    extern __shared__ float se[];             // [(TB+HALO) * ED]
    __shared__ int   shash[(TBEMB + PADL) * NH];
    __shared__ float swt[KW * ED];
    __shared__ float sg[ED], sb[ED];

    int tid = threadIdx.x;
    int b = blockIdx.y, t0 = blockIdx.x * TB;

    sg[tid] = lg[tid];
    sb[tid] = lb[tid];
#pragma unroll
    for (int k = 0; k < KW; k++) swt[k * ED + tid] = cw[tid * KW + k];

    // stage hash ids (coalesced); -1 marks out-of-range pad tokens
    for (int i = tid; i < (TB + HALO) * NH; i += 256) {
        int lt = i >> 3;
        int t = t0 - HALO + lt;
        shash[i] = (t >= 0) ? hashes[(b * TT + t) * NH + (i & 7)] : -1;
    }
    __syncthreads();

    // gather: warp = head, lane = dim; 41 independent coalesced 128B loads
    int h = tid >> 5, d = tid & 31;
    int off_h = offs[h];
#pragma unroll 8
    for (int lt = 0; lt < TB + HALO; lt++) {
        int row = shash[lt * NH + h];
        float v = (row >= 0) ? emb[(size_t)(row + off_h) * HD + d] : 0.f;
        se[lt * ED + tid] = v;
    }
    __syncthreads();

    int wid = tid >> 5, lane = tid & 31;
    for (int it = 0; it < TB / 8; it++) {
        int tok = it * 8 + wid;
        int lt = tok + HALO;
        float c[8], ev[8];
        float s = 0.f, q = 0.f;
#pragma unroll
        for (int j = 0; j < 8; j++) {
            int ch = lane + 32 * j;
            float a = 0.f;
#pragma unroll
            for (int k = 0; k < KW; k++)
                a += se[(lt - PADL + k * DILN) * ED + ch] * swt[k * ED + ch];
            c[j] = a;
            ev[j] = se[lt * ED + ch];
            s += a; q += a * a;
        }
#pragma unroll
        for (int o = 16; o; o >>= 1) {
            s += __shfl_xor_sync(0xffffffffu, s, o);
            q += __shfl_xor_sync(0xffffffffu, q, o);
        }
        float mean = s * (1.f / ED);
        float var  = q * (1.f / ED) - mean * mean;
        float rstd = rsqrtf(var + 1e-5f);
#pragma unroll
        for (int j = 0; j < 8; j++) {
            int ch = lane + 32 * j;
            float y = (c[j] - mean) * rstd * sg[ch] + sb[ch];
            float o = ev[j] + y * (1.f / (1.f + expf(-y)));
            gEh[(size_t)(b * TT + t0 + tok) * ED + ch] = __float2half_rn(o);
        }
    }
}

// =====================================================================
// Kernel 3/5: fp16 tensor GEMM NT (m16n8k16), 128x128 block (R9 geometry).
//   MODE 0: B = gWkh; epilogue -> 9 raw gate partials. MODE 1: B = gMh, scaled store.
// =====================================================================
#define LDSH 72
#define HBUF (128 * LDSH)                // halfs per operand buffer
#define GSM  (4 * HBUF * 2)              // 73728 B

template <int MODE>
__global__ __launch_bounds__(256, 2) void k_gemm(float* __restrict__ Cout,
                                                 const float* __restrict__ x,
                                                 const float* __restrict__ lkg,
                                                 const float* __restrict__ lkb,
                                                 const float* __restrict__ lqg,
                                                 const float* __restrict__ lqb) {
    extern __shared__ __half sh[];
    __half* As = sh;                     // [2][HBUF]
    __half* Bs = sh + 2 * HBUF;          // [2][HBUF]

    const __half* A  = gEh;
    const __half* Bp = (MODE == 0) ? gWkh : gMh;

    int bm = blockIdx.y * 128, bn = blockIdx.x * 128;
    int tid = threadIdx.x, lane = tid & 31, wid = tid >> 5;
    int wm = wid & 1, wn = wid >> 1;

    float acc[4][4][4];
#pragma unroll
    for (int mt = 0; mt < 4; mt++)
#pragma unroll
        for (int nt = 0; nt < 4; nt++)
#pragma unroll
            for (int r = 0; r < 4; r++) acc[mt][nt][r] = 0.f;

    uint32_t as0 = smem_u32(As), bs0 = smem_u32(Bs);
    uint32_t a_base = as0 + (((wm * 64 + (lane & 15)) * LDSH + (lane >> 4) * 8) << 1);
    uint32_t b_base = bs0 + (((wn * 32 + (lane >> 4) * 8 + (lane & 7)) * LDSH
                              + ((lane >> 3) & 1) * 8) << 1);

    auto issue = [&](int t) {
        int s = t & 1;
        uint32_t ao = as0 + s * (HBUF * 2);
        uint32_t bo = bs0 + s * (HBUF * 2);
        int kt = t * 64;
#pragma unroll
        for (int i = 0; i < 4; i++) {
            int idx = tid + 256 * i;
            int row = idx >> 3, q = idx & 7;
            cpa16(ao + ((row * LDSH + q * 8) << 1), A  + (size_t)(bm + row) * ED + kt + q * 8);
            cpa16(bo + ((row * LDSH + q * 8) << 1), Bp + (size_t)(bn + row) * ED + kt + q * 8);
        }
        cpa_commit();
    };

    issue(0);
    for (int t = 0; t < 4; t++) {
        int s = t & 1;
        if (t < 3) { issue(t + 1); cpa_wait<1>(); }
        else       { cpa_wait<0>(); }
        __syncthreads();
        uint32_t abuf = a_base + s * (HBUF * 2);
        uint32_t bbuf = b_base + s * (HBUF * 2);
#pragma unroll
        for (int ks = 0; ks < 4; ks++) {
            uint32_t a[4][4], b[2][4];
#pragma unroll
            for (int mt = 0; mt < 4; mt++)
                ldsm4(a[mt][0], a[mt][1], a[mt][2], a[mt][3],
                      abuf + ((mt * 16 * LDSH + ks * 16) << 1));
#pragma unroll
            for (int p = 0; p < 2; p++)
                ldsm4(b[p][0], b[p][1], b[p][2], b[p][3],
                      bbuf + ((p * 16 * LDSH + ks * 16) << 1));
#pragma unroll
            for (int mt = 0; mt < 4; mt++)
#pragma unroll
                for (int nt = 0; nt < 4; nt++) {
                    int p = nt >> 1, q = (nt & 1) * 2;
                    mma_f16(acc[mt][nt], a[mt], b[p][q], b[p][q + 1]);
                }
        }
        __syncthreads();
    }

    if (MODE == 1) {
#pragma unroll
        for (int mt = 0; mt < 4; mt++) {
            int r0 = bm + wm * 64 + mt * 16 + (lane >> 2);
            float s0 = gG[r0], s1 = gG[r0 + 8];
#pragma unroll
            for (int nt = 0; nt < 4; nt++) {
                int c0 = bn + wn * 32 + nt * 8 + (lane & 3) * 2;
                *(float2*)(Cout + (size_t)r0 * HID + c0) =
                    make_float2(acc[mt][nt][0] * s0, acc[mt][nt][1] * s0);
                *(float2*)(Cout + (size_t)(r0 + 8) * HID + c0) =
                    make_float2(acc[mt][nt][2] * s1, acc[mt][nt][3] * s1);
            }
        }
    } else {
        // 9 raw partials: P0=Σkp·a·x P1=Σkp·a P2=Σa·x P3=Σkp·b P4=Σc·x
        //                 P5=Σkp P6=Σkp² P7=Σx P8=Σx²  (a=lkg·lqg, b=lkg·lqb, c=lkb·lqg)
        float* sA   = (float*)sh;        // [128] per-col a
        float* sB   = sA + 128;          // [128]
        float* sC   = sB + 128;          // [128]
        float* sRed = sC + 128;          // [4][128][9]
        if (tid < 128) {
            int col = bn + tid;
            float g1 = lkg[col], q1 = lqg[col], b1 = lkb[col], q0 = lqb[col];
            sA[tid] = g1 * q1; sB[tid] = g1 * q0; sC[tid] = b1 * q1;
        }
        __syncthreads();
#pragma unroll
        for (int mt = 0; mt < 4; mt++) {
#pragma unroll
            for (int half = 0; half < 2; half++) {
                int rl = wm * 64 + mt * 16 + half * 8 + (lane >> 2);
                int row = bm + rl;
                float p[9];
#pragma unroll
                for (int j = 0; j < 9; j++) p[j] = 0.f;
#pragma unroll
                for (int nt = 0; nt < 4; nt++) {
#pragma unroll
                    for (int e = 0; e < 2; e++) {
                        int cl = wn * 32 + nt * 8 + (lane & 3) * 2 + e;
                        float kp = acc[mt][nt][half * 2 + e];
                        float xv = x[(size_t)row * HID + bn + cl];
                        float a = sA[cl], b = sB[cl], c = sC[cl];
                        float ax = a * xv;
                        p[0] += kp * ax;
                        p[1] += kp * a;
                        p[2] += ax;
                        p[3] += kp * b;
                        p[4] += c * xv;
                        p[5] += kp;
                        p[6] += kp * kp;
                        p[7] += xv;
                        p[8] += xv * xv;
                    }
                }
#pragma unroll
                for (int o = 1; o <= 2; o <<= 1)
#pragma unroll
                    for (int j = 0; j < 9; j++)
                        p[j] += __shfl_xor_sync(0xffffffffu, p[j], o);
                if ((lane & 3) == 0) {
                    float* d = sRed + ((size_t)wn * 128 + rl) * 9;
#pragma unroll
                    for (int j = 0; j < 9; j++) d[j] = p[j];
                }
            }
        }
        __syncthreads();
        for (int idx = tid; idx < 128 * 9; idx += 256) {
            int rl = idx / 9, j = idx - rl * 9;
            float s = sRed[((size_t)0 * 128 + rl) * 9 + j]
                    + sRed[((size_t)1 * 128 + rl) * 9 + j]
                    + sRed[((size_t)2 * 128 + rl) * 9 + j]
                    + sRed[((size_t)3 * 128 + rl) * 9 + j];
            gPart[(((size_t)(bm + rl)) * 16 + blockIdx.x) * 16 + j] = s;
        }
    }
}

// =====================================================================
// Kernel 4: finalize gate (LN-weight constants computed in-block)
// =====================================================================
__global__ __launch_bounds__(256) void k_gfin(const float* __restrict__ lkg,
                                              const float* __restrict__ lkb,
                                              const float* __restrict__ lqg,
                                              const float* __restrict__ lqb) {
    __shared__ float cred[4][8];
    __shared__ float4 Cs;
    int tid = threadIdx.x, lane = tid & 31, wid = tid >> 5;

    float sa = 0.f, sb = 0.f, sc = 0.f, sd = 0.f;
    for (int c = tid; c < HID; c += 256) {
        float g1 = lkg[c], b1 = lkb[c], q1 = lqg[c], q0 = lqb[c];
        sa += g1 * q1; sb += g1 * q0; sc += b1 * q1; sd += b1 * q0;
    }
#pragma unroll
    for (int o = 16; o; o >>= 1) {
        sa += __shfl_xor_sync(0xffffffffu, sa, o);
        sb += __shfl_xor_sync(0xffffffffu, sb, o);
        sc += __shfl_xor_sync(0xffffffffu, sc, o);
        sd += __shfl_xor_sync(0xffffffffu, sd, o);
    }
    if (lane == 0) { cred[0][wid] = sa; cred[1][wid] = sb; cred[2][wid] = sc; cred[3][wid] = sd; }
    __syncthreads();
    if (tid == 0) {
        float a = 0.f, b = 0.f, c = 0.f, d = 0.f;
#pragma unroll
        for (int w = 0; w < 8; w++) { a += cred[0][w]; b += cred[1][w]; c += cred[2][w]; d += cred[3][w]; }
        Cs = make_float4(a, b, c, d);
    }
    __syncthreads();
    float4 C = Cs;

    int row = blockIdx.x * 256 + tid;
    float P[9];
#pragma unroll
    for (int j = 0; j < 9; j++) P[j] = 0.f;
#pragma unroll
    for (int nb = 0; nb < 16; nb++) {
        const float* p = gPart + (((size_t)row) * 16 + nb) * 16;
#pragma unroll
        for (int j = 0; j < 9; j++) P[j] += p[j];
    }
    float mk = P[5] * (1.f / HID);
    float rk = rsqrtf(P[6] * (1.f / HID) - mk * mk + 1e-5f);
    float mx = P[7] * (1.f / HID);
    float rx = rsqrtf(P[8] * (1.f / HID) - mx * mx + 1e-5f);
    float dot = rk * rx * (P[0] - mx * P[1] - mk * P[2] + mk * mx * C.x)
              + rk * (P[3] - mk * C.y)
              + rx * (P[4] - mx * C.z)
              + C.w;
    float s = dot * rsqrtf((float)HID);
    float a = fmaxf(fabsf(s), 1e-6f);
    float sgn = (s > 0.f) ? 1.f : ((s < 0.f) ? -1.f : 0.f);
    gG[row] = 1.f / (1.f + expf(-sqrtf(a) * sgn));
}

// =====================================================================
extern "C" void kernel_launch(void* const* d_in, const int* in_sizes, int n_in,
                              void* d_out, int out_size) {
    const float* x      = (const float*)d_in[0];
    const int*   hashes = (const int*)  d_in[1];
    const int*   offs   = (const int*)  d_in[2];
    const float* emb    = (const float*)d_in[3];
    const float* convw  = (const float*)d_in[4];
    const float* lncg   = (const float*)d_in[5];
    const float* lncb   = (const float*)d_in[6];
    const float* Wk     = (const float*)d_in[7];
    const float* Wv     = (const float*)d_in[8];
    const float* Wo     = (const float*)d_in[9];
    const float* lkg    = (const float*)d_in[10];
    const float* lkb    = (const float*)d_in[11];
    const float* lqg    = (const float*)d_in[12];
    const float* lqb    = (const float*)d_in[13];
    float* out = (float*)d_out;

    cudaFuncSetAttribute(k_gemm<0>, cudaFuncAttributeMaxDynamicSharedMemorySize, GSM);
    cudaFuncSetAttribute(k_gemm<1>, cudaFuncAttributeMaxDynamicSharedMemorySize, GSM);
    cudaFuncSetAttribute(k_embed,   cudaFuncAttributeMaxDynamicSharedMemorySize, ESM);

    // 0) M = Wo @ Wv (tf32 tensor cores, split-K=4) -> fp16 gMh;  Wk -> fp16
    k_matM5<<<dim3(4, 16, 4), 256>>>(Wo, Wv);
    k_matred<<<512, 256>>>();
    k_cvtWk<<<HID * ED / 1024, 256>>>(Wk);

    // 1) gather + conv + LN + SiLU -> gEh  (se tile in dynamic smem)
    k_embed<<<dim3(TT / TBEMB, BB), 256, ESM>>>(hashes, offs, emb, convw, lncg, lncb);

    // 2) KP GEMM (fp16, 128x128 tiles) with fused gate partials + x stats
    k_gemm<0><<<dim3(HID / 128, BT / 128), 256, GSM>>>(nullptr, x, lkg, lkb, lqg, lqb);

    // 3) finalize gate (constants inlined)
    k_gfin<<<BT / 256, 256>>>(lkg, lkb, lqg, lqb);

    // 4) out = diag(g) * (gEh @ M^T)
    k_gemm<1><<<dim3(HID / 128, BT / 128), 256, GSM>>>(out, x, lkg, lkb, lqg, lqb);
}

// round 13
// speedup vs baseline: 1.0583x; 1.0339x over previous
#include <cuda_runtime.h>
#include <cuda_fp16.h>
#include <math.h>
#include <stdint.h>

// ---------------- problem constants ----------------
#define BB   4
#define TT   4096
#define BT   (BB*TT)      // 16384 tokens
#define HID  2048
#define ED   256          // engram dim
#define NH   8            // total hash heads
#define HD   32           // head dim
#define KW   4            // conv kernel
#define DILN 3            // dilation
#define PADL 9            // causal left pad

// ---------------- scratch (device globals; no allocation) ----------------
__device__ __align__(16) __half gEh [(size_t)BT * ED];      // e' fp16 (8 MB)
__device__ __align__(16) __half gMh [(size_t)HID * ED];     // M = Wo@Wv fp16 (1 MB)
__device__ __align__(16) __half gWkh[(size_t)HID * ED];     // Wk fp16 (1 MB)
__device__ float gG[BT];                                    // per-token gate
__device__ __align__(16) float gPart[(size_t)BT * 16 * 16]; // gate partials (16 MB)
__device__ __align__(16) float gMscr[(size_t)4 * HID * ED]; // matM split-K scratch (8 MB)
                                                            // (separate from gPart: matM runs
                                                            //  CONCURRENTLY with gemm0 epilogue)

// ---------------- helpers ----------------------------------------------
__device__ __forceinline__ uint32_t f2tf32(float f) {
    uint32_t u; asm("cvt.rna.tf32.f32 %0, %1;" : "=r"(u) : "f"(f)); return u;
}
__device__ __forceinline__ uint32_t smem_u32(const void* p) {
    uint32_t r;
    asm("{ .reg .u64 t; cvta.to.shared.u64 t, %1; cvt.u32.u64 %0, t; }" : "=r"(r) : "l"(p));
    return r;
}
__device__ __forceinline__ void ldsm4(uint32_t& r0, uint32_t& r1, uint32_t& r2, uint32_t& r3,
                                      uint32_t addr) {
    asm volatile("ldmatrix.sync.aligned.m8n8.x4.shared.b16 {%0,%1,%2,%3}, [%4];"
                 : "=r"(r0), "=r"(r1), "=r"(r2), "=r"(r3) : "r"(addr));
}
__device__ __forceinline__ void mma_f16(float* c, const uint32_t* a, uint32_t b0, uint32_t b1) {
    asm volatile("mma.sync.aligned.m16n8k16.row.col.f32.f16.f16.f32 "
                 "{%0,%1,%2,%3}, {%4,%5,%6,%7}, {%8,%9}, {%0,%1,%2,%3};"
                 : "+f"(c[0]), "+f"(c[1]), "+f"(c[2]), "+f"(c[3])
                 : "r"(a[0]), "r"(a[1]), "r"(a[2]), "r"(a[3]), "r"(b0), "r"(b1));
}
__device__ __forceinline__ void mma_tf32(float* c, const uint32_t* a, uint32_t b0, uint32_t b1) {
    asm volatile("mma.sync.aligned.m16n8k8.row.col.f32.tf32.tf32.f32 "
                 "{%0,%1,%2,%3}, {%4,%5,%6,%7}, {%8,%9}, {%0,%1,%2,%3};"
                 : "+f"(c[0]), "+f"(c[1]), "+f"(c[2]), "+f"(c[3])
                 : "r"(a[0]), "r"(a[1]), "r"(a[2]), "r"(a[3]), "r"(b0), "r"(b1));
}
__device__ __forceinline__ void cpa16(uint32_t dst, const void* src) {
    asm volatile("cp.async.ca.shared.global [%0], [%1], 16;" :: "r"(dst), "l"(src));
}
__device__ __forceinline__ void cpa_commit() { asm volatile("cp.async.commit_group;"); }
template <int N> __device__ __forceinline__ void cpa_wait() {
    asm volatile("cp.async.wait_group %0;" :: "n"(N) : "memory");
}

// =====================================================================
// Kernel 0: matM split-K (tf32 tensor cores) -> gMscr
// =====================================================================
#define MLDS 36
__global__ __launch_bounds__(256) void k_matM5(const float* __restrict__ Wo,
                                               const float* __restrict__ Wv) {
    __shared__ uint32_t As[128 * MLDS];
    __shared__ uint32_t Bs[64 * MLDS];
    int bn = blockIdx.x * 64;
    int bm = blockIdx.y * 128;
    int K0 = blockIdx.z * 512;
    int tid = threadIdx.x, lane = tid & 31, wid = tid >> 5;
    int wm = wid & 3, wn = wid >> 2;

    float acc[2][4][4];
#pragma unroll
    for (int mt = 0; mt < 2; mt++)
#pragma unroll
        for (int nt = 0; nt < 4; nt++)
#pragma unroll
            for (int r = 0; r < 4; r++) acc[mt][nt][r] = 0.f;

    uint32_t as0 = smem_u32(As), bs0 = smem_u32(Bs);
    uint32_t a_base = as0 + (((wm * 32 + (lane & 15)) * MLDS + (lane >> 4) * 4) << 2);
    uint32_t b_base = bs0 + (((wn * 32 + (lane >> 4) * 8 + (lane & 7)) * MLDS
                              + ((lane >> 3) & 1) * 4) << 2);

    for (int kt = 0; kt < 512; kt += 32) {
#pragma unroll
        for (int i = 0; i < 4; i++) {
            int idx = tid + 256 * i;
            int r = idx >> 3, q = idx & 7;
            float4 v = *(const float4*)(Wo + (size_t)(bm + r) * 2048 + K0 + kt + q * 4);
            uint32_t* d = &As[r * MLDS + q * 4];
            d[0] = f2tf32(v.x); d[1] = f2tf32(v.y); d[2] = f2tf32(v.z); d[3] = f2tf32(v.w);
        }
#pragma unroll
        for (int p = 0; p < 2; p++) {
            int kk = (tid >> 4) + p * 16;
            int c4 = (tid & 15) * 4;
            float4 v = *(const float4*)(Wv + (size_t)(K0 + kt + kk) * 256 + bn + c4);
            Bs[(c4 + 0) * MLDS + kk] = f2tf32(v.x);
            Bs[(c4 + 1) * MLDS + kk] = f2tf32(v.y);
            Bs[(c4 + 2) * MLDS + kk] = f2tf32(v.z);
            Bs[(c4 + 3) * MLDS + kk] = f2tf32(v.w);
        }
        __syncthreads();
#pragma unroll
        for (int ks = 0; ks < 4; ks++) {
            uint32_t a[2][4], b[2][4];
#pragma unroll
            for (int mt = 0; mt < 2; mt++)
                ldsm4(a[mt][0], a[mt][1], a[mt][2], a[mt][3],
                      a_base + ((mt * 16 * MLDS + ks * 8) << 2));
#pragma unroll
            for (int p = 0; p < 2; p++)
                ldsm4(b[p][0], b[p][1], b[p][2], b[p][3],
                      b_base + ((p * 16 * MLDS + ks * 8) << 2));
#pragma unroll
            for (int mt = 0; mt < 2; mt++)
#pragma unroll
                for (int nt = 0; nt < 4; nt++) {
                    int p = nt >> 1, s = (nt & 1) * 2;
                    mma_tf32(acc[mt][nt], a[mt], b[p][s], b[p][s + 1]);
                }
        }
        __syncthreads();
    }

    float* pm = gMscr + (size_t)blockIdx.z * (2048 * 256);
#pragma unroll
    for (int mt = 0; mt < 2; mt++) {
        int r0 = bm + wm * 32 + mt * 16 + (lane >> 2);
#pragma unroll
        for (int nt = 0; nt < 4; nt++) {
            int c0 = bn + wn * 32 + nt * 8 + (lane & 3) * 2;
            *(float2*)(pm + (size_t)r0 * 256 + c0) =
                make_float2(acc[mt][nt][0], acc[mt][nt][1]);
            *(float2*)(pm + (size_t)(r0 + 8) * 256 + c0) =
                make_float2(acc[mt][nt][2], acc[mt][nt][3]);
        }
    }
}

__global__ __launch_bounds__(256) void k_matred() {
    int i = (blockIdx.x * 256 + threadIdx.x) * 4;
    float4 s = *(const float4*)(gMscr + i);
#pragma unroll
    for (int kc = 1; kc < 4; kc++) {
        float4 v = *(const float4*)(gMscr + (size_t)kc * (2048 * 256) + i);
        s.x += v.x; s.y += v.y; s.z += v.z; s.w += v.w;
    }
    *(__half2*)(gMh + i)     = __floats2half2_rn(s.x, s.y);
    *(__half2*)(gMh + i + 2) = __floats2half2_rn(s.z, s.w);
}

__global__ __launch_bounds__(256) void k_cvtWk(const float* __restrict__ Wk) {
    int i = (blockIdx.x * 256 + threadIdx.x) * 4;
    float4 v = *(const float4*)(Wk + i);
    *(__half2*)(gWkh + i)     = __floats2half2_rn(v.x, v.y);
    *(__half2*)(gWkh + i + 2) = __floats2half2_rn(v.z, v.w);
}

// =====================================================================
// Kernel 1: hash-gather + dilated causal depthwise conv + LN + SiLU -> gEh
//   (reverted to the empirically-fastest R10 form: direct gather, static smem)
// =====================================================================
__global__ __launch_bounds__(256) void k_embed(const int* __restrict__ hashes,
                                               const int* __restrict__ offs,
                                               const float* __restrict__ emb,
                                               const float* __restrict__ cw,
                                               const float* __restrict__ lg,
                                               const float* __restrict__ lb) {
    const int TB = 32, HALO = PADL;
    __shared__ float se[(TB + HALO) * ED];
    __shared__ float swt[KW * ED];
    __shared__ float sg[ED], sb[ED];

    int tid = threadIdx.x;
    int b = blockIdx.y, t0 = blockIdx.x * TB;

    sg[tid] = lg[tid];
    sb[tid] = lb[tid];
#pragma unroll
    for (int k = 0; k < KW; k++) swt[k * ED + tid] = cw[tid * KW + k];

    int h = tid >> 5, d = tid & 31;
    int off_h = offs[h];
    for (int lt = 0; lt < TB + HALO; lt++) {
        int t = t0 - HALO + lt;
        float v = 0.f;
        if (t >= 0) {
            int row = hashes[(b * TT + t) * NH + h] + off_h;
            v = emb[(size_t)row * HD + d];
        }
        se[lt * ED + tid] = v;
    }
    __syncthreads();

    int wid = tid >> 5, lane = tid & 31;
    for (int it = 0; it < TB / 8; it++) {
        int tok = it * 8 + wid;
        int lt = tok + HALO;
        float c[8], ev[8];
        float s = 0.f, q = 0.f;
#pragma unroll
        for (int j = 0; j < 8; j++) {
            int ch = lane + 32 * j;
            float a = 0.f;
#pragma unroll
            for (int k = 0; k < KW; k++)
                a += se[(lt - PADL + k * DILN) * ED + ch] * swt[k * ED + ch];
            c[j] = a;
            ev[j] = se[lt * ED + ch];
            s += a; q += a * a;
        }
#pragma unroll
        for (int o = 16; o; o >>= 1) {
            s += __shfl_xor_sync(0xffffffffu, s, o);
            q += __shfl_xor_sync(0xffffffffu, q, o);
        }
        float mean = s * (1.f / ED);
        float var  = q * (1.f / ED) - mean * mean;
        float rstd = rsqrtf(var + 1e-5f);
#pragma unroll
        for (int j = 0; j < 8; j++) {
            int ch = lane + 32 * j;
            float y = (c[j] - mean) * rstd * sg[ch] + sb[ch];
            float o = ev[j] + y * (1.f / (1.f + expf(-y)));
            gEh[(size_t)(b * TT + t0 + tok) * ED + ch] = __float2half_rn(o);
        }
    }
}

// =====================================================================
// Kernel 3/5: fp16 tensor GEMM NT (m16n8k16), 128x128 block (R9 geometry).
//   MODE 0: B = gWkh; epilogue -> 9 raw gate partials. MODE 1: B = gMh, scaled store.
// =====================================================================
#define LDSH 72
#define HBUF (128 * LDSH)                // halfs per operand buffer
#define GSM  (4 * HBUF * 2)              // 73728 B

template <int MODE>
__global__ __launch_bounds__(256, 2) void k_gemm(float* __restrict__ Cout,
                                                 const float* __restrict__ x,
                                                 const float* __restrict__ lkg,
                                                 const float* __restrict__ lkb,
                                                 const float* __restrict__ lqg,
                                                 const float* __restrict__ lqb) {
    extern __shared__ __half sh[];
    __half* As = sh;                     // [2][HBUF]
    __half* Bs = sh + 2 * HBUF;          // [2][HBUF]

    const __half* A  = gEh;
    const __half* Bp = (MODE == 0) ? gWkh : gMh;

    int bm = blockIdx.y * 128, bn = blockIdx.x * 128;
    int tid = threadIdx.x, lane = tid & 31, wid = tid >> 5;
    int wm = wid & 1, wn = wid >> 1;

    float acc[4][4][4];
#pragma unroll
    for (int mt = 0; mt < 4; mt++)
#pragma unroll
        for (int nt = 0; nt < 4; nt++)
#pragma unroll
            for (int r = 0; r < 4; r++) acc[mt][nt][r] = 0.f;

    uint32_t as0 = smem_u32(As), bs0 = smem_u32(Bs);
    uint32_t a_base = as0 + (((wm * 64 + (lane & 15)) * LDSH + (lane >> 4) * 8) << 1);
    uint32_t b_base = bs0 + (((wn * 32 + (lane >> 4) * 8 + (lane & 7)) * LDSH
                              + ((lane >> 3) & 1) * 8) << 1);

    auto issue = [&](int t) {
        int s = t & 1;
        uint32_t ao = as0 + s * (HBUF * 2);
        uint32_t bo = bs0 + s * (HBUF * 2);
        int kt = t * 64;
#pragma unroll
        for (int i = 0; i < 4; i++) {
            int idx = tid + 256 * i;
            int row = idx >> 3, q = idx & 7;
            cpa16(ao + ((row * LDSH + q * 8) << 1), A  + (size_t)(bm + row) * ED + kt + q * 8);
            cpa16(bo + ((row * LDSH + q * 8) << 1), Bp + (size_t)(bn + row) * ED + kt + q * 8);
        }
        cpa_commit();
    };

    issue(0);
    for (int t = 0; t < 4; t++) {
        int s = t & 1;
        if (t < 3) { issue(t + 1); cpa_wait<1>(); }
        else       { cpa_wait<0>(); }
        __syncthreads();
        uint32_t abuf = a_base + s * (HBUF * 2);
        uint32_t bbuf = b_base + s * (HBUF * 2);
#pragma unroll
        for (int ks = 0; ks < 4; ks++) {
            uint32_t a[4][4], b[2][4];
#pragma unroll
            for (int mt = 0; mt < 4; mt++)
                ldsm4(a[mt][0], a[mt][1], a[mt][2], a[mt][3],
                      abuf + ((mt * 16 * LDSH + ks * 16) << 1));
#pragma unroll
            for (int p = 0; p < 2; p++)
                ldsm4(b[p][0], b[p][1], b[p][2], b[p][3],
                      bbuf + ((p * 16 * LDSH + ks * 16) << 1));
#pragma unroll
            for (int mt = 0; mt < 4; mt++)
#pragma unroll
                for (int nt = 0; nt < 4; nt++) {
                    int p = nt >> 1, q = (nt & 1) * 2;
                    mma_f16(acc[mt][nt], a[mt], b[p][q], b[p][q + 1]);
                }
        }
        __syncthreads();
    }

    if (MODE == 1) {
#pragma unroll
        for (int mt = 0; mt < 4; mt++) {
            int r0 = bm + wm * 64 + mt * 16 + (lane >> 2);
            float s0 = gG[r0], s1 = gG[r0 + 8];
#pragma unroll
            for (int nt = 0; nt < 4; nt++) {
                int c0 = bn + wn * 32 + nt * 8 + (lane & 3) * 2;
                *(float2*)(Cout + (size_t)r0 * HID + c0) =
                    make_float2(acc[mt][nt][0] * s0, acc[mt][nt][1] * s0);
                *(float2*)(Cout + (size_t)(r0 + 8) * HID + c0) =
                    make_float2(acc[mt][nt][2] * s1, acc[mt][nt][3] * s1);
            }
        }
    } else {
        // 9 raw partials: P0=Σkp·a·x P1=Σkp·a P2=Σa·x P3=Σkp·b P4=Σc·x
        //                 P5=Σkp P6=Σkp² P7=Σx P8=Σx²  (a=lkg·lqg, b=lkg·lqb, c=lkb·lqg)
        float* sA   = (float*)sh;        // [128] per-col a
        float* sB   = sA + 128;          // [128]
        float* sC   = sB + 128;          // [128]
        float* sRed = sC + 128;          // [4][128][9]
        if (tid < 128) {
            int col = bn + tid;
            float g1 = lkg[col], q1 = lqg[col], b1 = lkb[col], q0 = lqb[col];
            sA[tid] = g1 * q1; sB[tid] = g1 * q0; sC[tid] = b1 * q1;
        }
        __syncthreads();
#pragma unroll
        for (int mt = 0; mt < 4; mt++) {
#pragma unroll
            for (int half = 0; half < 2; half++) {
                int rl = wm * 64 + mt * 16 + half * 8 + (lane >> 2);
                int row = bm + rl;
                float p[9];
#pragma unroll
                for (int j = 0; j < 9; j++) p[j] = 0.f;
#pragma unroll
                for (int nt = 0; nt < 4; nt++) {
#pragma unroll
                    for (int e = 0; e < 2; e++) {
                        int cl = wn * 32 + nt * 8 + (lane & 3) * 2 + e;
                        float kp = acc[mt][nt][half * 2 + e];
                        float xv = x[(size_t)row * HID + bn + cl];
                        float a = sA[cl], b = sB[cl], c = sC[cl];
                        float ax = a * xv;
                        p[0] += kp * ax;
                        p[1] += kp * a;
                        p[2] += ax;
                        p[3] += kp * b;
                        p[4] += c * xv;
                        p[5] += kp;
                        p[6] += kp * kp;
                        p[7] += xv;
                        p[8] += xv * xv;
                    }
                }
#pragma unroll
                for (int o = 1; o <= 2; o <<= 1)
#pragma unroll
                    for (int j = 0; j < 9; j++)
                        p[j] += __shfl_xor_sync(0xffffffffu, p[j], o);
                if ((lane & 3) == 0) {
                    float* d = sRed + ((size_t)wn * 128 + rl) * 9;
#pragma unroll
                    for (int j = 0; j < 9; j++) d[j] = p[j];
                }
            }
        }
        __syncthreads();
        for (int idx = tid; idx < 128 * 9; idx += 256) {
            int rl = idx / 9, j = idx - rl * 9;
            float s = sRed[((size_t)0 * 128 + rl) * 9 + j]
                    + sRed[((size_t)1 * 128 + rl) * 9 + j]
                    + sRed[((size_t)2 * 128 + rl) * 9 + j]
                    + sRed[((size_t)3 * 128 + rl) * 9 + j];
            gPart[(((size_t)(bm + rl)) * 16 + blockIdx.x) * 16 + j] = s;
        }
    }
}

// =====================================================================
// Kernel 4: finalize gate (LN-weight constants computed in-block)
// =====================================================================
__global__ __launch_bounds__(256) void k_gfin(const float* __restrict__ lkg,
                                              const float* __restrict__ lkb,
                                              const float* __restrict__ lqg,
                                              const float* __restrict__ lqb) {
    __shared__ float cred[4][8];
    __shared__ float4 Cs;
    int tid = threadIdx.x, lane = tid & 31, wid = tid >> 5;

    float sa = 0.f, sb = 0.f, sc = 0.f, sd = 0.f;
    for (int c = tid; c < HID; c += 256) {
        float g1 = lkg[c], b1 = lkb[c], q1 = lqg[c], q0 = lqb[c];
        sa += g1 * q1; sb += g1 * q0; sc += b1 * q1; sd += b1 * q0;
    }
#pragma unroll
    for (int o = 16; o; o >>= 1) {
        sa += __shfl_xor_sync(0xffffffffu, sa, o);
        sb += __shfl_xor_sync(0xffffffffu, sb, o);
        sc += __shfl_xor_sync(0xffffffffu, sc, o);
        sd += __shfl_xor_sync(0xffffffffu, sd, o);
    }
    if (lane == 0) { cred[0][wid] = sa; cred[1][wid] = sb; cred[2][wid] = sc; cred[3][wid] = sd; }
    __syncthreads();
    if (tid == 0) {
        float a = 0.f, b = 0.f, c = 0.f, d = 0.f;
#pragma unroll
        for (int w = 0; w < 8; w++) { a += cred[0][w]; b += cred[1][w]; c += cred[2][w]; d += cred[3][w]; }
        Cs = make_float4(a, b, c, d);
    }
    __syncthreads();
    float4 C = Cs;

    int row = blockIdx.x * 256 + tid;
    float P[9];
#pragma unroll
    for (int j = 0; j < 9; j++) P[j] = 0.f;
#pragma unroll
    for (int nb = 0; nb < 16; nb++) {
        const float* p = gPart + (((size_t)row) * 16 + nb) * 16;
#pragma unroll
        for (int j = 0; j < 9; j++) P[j] += p[j];
    }
    float mk = P[5] * (1.f / HID);
    float rk = rsqrtf(P[6] * (1.f / HID) - mk * mk + 1e-5f);
    float mx = P[7] * (1.f / HID);
    float rx = rsqrtf(P[8] * (1.f / HID) - mx * mx + 1e-5f);
    float dot = rk * rx * (P[0] - mx * P[1] - mk * P[2] + mk * mx * C.x)
              + rk * (P[3] - mk * C.y)
              + rx * (P[4] - mx * C.z)
              + C.w;
    float s = dot * rsqrtf((float)HID);
    float a = fmaxf(fabsf(s), 1e-6f);
    float sgn = (s > 0.f) ? 1.f : ((s < 0.f) ? -1.f : 0.f);
    gG[row] = 1.f / (1.f + expf(-sqrtf(a) * sgn));
}

// =====================================================================
extern "C" void kernel_launch(void* const* d_in, const int* in_sizes, int n_in,
                              void* d_out, int out_size) {
    const float* x      = (const float*)d_in[0];
    const int*   hashes = (const int*)  d_in[1];
    const int*   offs   = (const int*)  d_in[2];
    const float* emb    = (const float*)d_in[3];
    const float* convw  = (const float*)d_in[4];
    const float* lncg   = (const float*)d_in[5];
    const float* lncb   = (const float*)d_in[6];
    const float* Wk     = (const float*)d_in[7];
    const float* Wv     = (const float*)d_in[8];
    const float* Wo     = (const float*)d_in[9];
    const float* lkg    = (const float*)d_in[10];
    const float* lkb    = (const float*)d_in[11];
    const float* lqg    = (const float*)d_in[12];
    const float* lqb    = (const float*)d_in[13];
    float* out = (float*)d_out;

    cudaFuncSetAttribute(k_gemm<0>, cudaFuncAttributeMaxDynamicSharedMemorySize, GSM);
    cudaFuncSetAttribute(k_gemm<1>, cudaFuncAttributeMaxDynamicSharedMemorySize, GSM);

    // Lazily created stream/events (resource setup only; the WORK issued per
    // call is identical every time, so determinism/capture rules hold).
    static cudaStream_t sideS = nullptr;
    static cudaEvent_t evFork = nullptr, evJoin = nullptr;
    if (sideS == nullptr) {
        cudaStreamCreateWithFlags(&sideS, cudaStreamNonBlocking);
        cudaEventCreateWithFlags(&evFork, cudaEventDisableTiming);
        cudaEventCreateWithFlags(&evJoin, cudaEventDisableTiming);
    }

    // ---- side stream: M = Wo @ Wv (only needed by the LAST gemm) ----
    cudaEventRecord(evFork, 0);
    cudaStreamWaitEvent(sideS, evFork, 0);
    k_matM5<<<dim3(4, 16, 4), 256, 0, sideS>>>(Wo, Wv);
    k_matred<<<512, 256, 0, sideS>>>();
    cudaEventRecord(evJoin, sideS);

    // ---- main stream ----
    k_cvtWk<<<HID * ED / 1024, 256>>>(Wk);
    k_embed<<<dim3(TT / 32, BB), 256>>>(hashes, offs, emb, convw, lncg, lncb);
    k_gemm<0><<<dim3(HID / 128, BT / 128), 256, GSM>>>(nullptr, x, lkg, lkb, lqg, lqb);
    k_gfin<<<BT / 256, 256>>>(lkg, lkb, lqg, lqb);

    cudaStreamWaitEvent(0, evJoin, 0);   // join matM chain before the value GEMM
    k_gemm<1><<<dim3(HID / 128, BT / 128), 256, GSM>>>(out, x, lkg, lkb, lqg, lqb);
}

// round 15
// speedup vs baseline: 1.0654x; 1.0067x over previous
#include <cuda_runtime.h>
#include <cuda_fp16.h>
#include <math.h>
#include <stdint.h>

// ---------------- problem constants ----------------
#define BB   4
#define TT   4096
#define BT   (BB*TT)      // 16384 tokens
#define HID  2048
#define ED   256          // engram dim
#define NH   8            // total hash heads
#define HD   32           // head dim
#define KW   4            // conv kernel
#define DILN 3            // dilation
#define PADL 9            // causal left pad

// ---------------- scratch (device globals; no allocation) ----------------
__device__ __align__(16) __half gEh [(size_t)BT * ED];      // e' fp16 (8 MB)
__device__ __align__(16) __half gMh [(size_t)HID * ED];     // M = Wo@Wv fp16 (1 MB)
__device__ __align__(16) __half gWkh[(size_t)HID * ED];     // Wk fp16 (1 MB)
__device__ float gG[BT];                                    // per-token gate
__device__ __align__(16) float gPart[(size_t)BT * 16 * 16]; // gate partials (16 MB)
__device__ __align__(16) float gMscr[(size_t)4 * HID * ED]; // matM split-K scratch (8 MB)

// ---------------- helpers ----------------------------------------------
__device__ __forceinline__ uint32_t f2tf32(float f) {
    uint32_t u; asm("cvt.rna.tf32.f32 %0, %1;" : "=r"(u) : "f"(f)); return u;
}
__device__ __forceinline__ uint32_t smem_u32(const void* p) {
    uint32_t r;
    asm("{ .reg .u64 t; cvta.to.shared.u64 t, %1; cvt.u32.u64 %0, t; }" : "=r"(r) : "l"(p));
    return r;
}
__device__ __forceinline__ void ldsm4(uint32_t& r0, uint32_t& r1, uint32_t& r2, uint32_t& r3,
                                      uint32_t addr) {
    asm volatile("ldmatrix.sync.aligned.m8n8.x4.shared.b16 {%0,%1,%2,%3}, [%4];"
                 : "=r"(r0), "=r"(r1), "=r"(r2), "=r"(r3) : "r"(addr));
}
__device__ __forceinline__ void mma_f16(float* c, const uint32_t* a, uint32_t b0, uint32_t b1) {
    asm volatile("mma.sync.aligned.m16n8k16.row.col.f32.f16.f16.f32 "
                 "{%0,%1,%2,%3}, {%4,%5,%6,%7}, {%8,%9}, {%0,%1,%2,%3};"
                 : "+f"(c[0]), "+f"(c[1]), "+f"(c[2]), "+f"(c[3])
                 : "r"(a[0]), "r"(a[1]), "r"(a[2]), "r"(a[3]), "r"(b0), "r"(b1));
}
__device__ __forceinline__ void mma_tf32(float* c, const uint32_t* a, uint32_t b0, uint32_t b1) {
    asm volatile("mma.sync.aligned.m16n8k8.row.col.f32.tf32.tf32.f32 "
                 "{%0,%1,%2,%3}, {%4,%5,%6,%7}, {%8,%9}, {%0,%1,%2,%3};"
                 : "+f"(c[0]), "+f"(c[1]), "+f"(c[2]), "+f"(c[3])
                 : "r"(a[0]), "r"(a[1]), "r"(a[2]), "r"(a[3]), "r"(b0), "r"(b1));
}
__device__ __forceinline__ void cpa16(uint32_t dst, const void* src) {
    asm volatile("cp.async.ca.shared.global [%0], [%1], 16;" :: "r"(dst), "l"(src));
}
__device__ __forceinline__ void cpa_commit() { asm volatile("cp.async.commit_group;"); }
template <int N> __device__ __forceinline__ void cpa_wait() {
    asm volatile("cp.async.wait_group %0;" :: "n"(N) : "memory");
}

// =====================================================================
// Kernel 0: matM split-K (tf32 tensor cores) -> gMscr
// =====================================================================
#define MLDS 36
__global__ __launch_bounds__(256) void k_matM5(const float* __restrict__ Wo,
                                               const float* __restrict__ Wv) {
    __shared__ uint32_t As[128 * MLDS];
    __shared__ uint32_t Bs[64 * MLDS];
    int bn = blockIdx.x * 64;
    int bm = blockIdx.y * 128;
    int K0 = blockIdx.z * 512;
    int tid = threadIdx.x, lane = tid & 31, wid = tid >> 5;
    int wm = wid & 3, wn = wid >> 2;

    float acc[2][4][4];
#pragma unroll
    for (int mt = 0; mt < 2; mt++)
#pragma unroll
        for (int nt = 0; nt < 4; nt++)
#pragma unroll
            for (int r = 0; r < 4; r++) acc[mt][nt][r] = 0.f;

    uint32_t as0 = smem_u32(As), bs0 = smem_u32(Bs);
    uint32_t a_base = as0 + (((wm * 32 + (lane & 15)) * MLDS + (lane >> 4) * 4) << 2);
    uint32_t b_base = bs0 + (((wn * 32 + (lane >> 4) * 8 + (lane & 7)) * MLDS
                              + ((lane >> 3) & 1) * 4) << 2);

    for (int kt = 0; kt < 512; kt += 32) {
#pragma unroll
        for (int i = 0; i < 4; i++) {
            int idx = tid + 256 * i;
            int r = idx >> 3, q = idx & 7;
            float4 v = *(const float4*)(Wo + (size_t)(bm + r) * 2048 + K0 + kt + q * 4);
            uint32_t* d = &As[r * MLDS + q * 4];
            d[0] = f2tf32(v.x); d[1] = f2tf32(v.y); d[2] = f2tf32(v.z); d[3] = f2tf32(v.w);
        }
#pragma unroll
        for (int p = 0; p < 2; p++) {
            int kk = (tid >> 4) + p * 16;
            int c4 = (tid & 15) * 4;
            float4 v = *(const float4*)(Wv + (size_t)(K0 + kt + kk) * 256 + bn + c4);
            Bs[(c4 + 0) * MLDS + kk] = f2tf32(v.x);
            Bs[(c4 + 1) * MLDS + kk] = f2tf32(v.y);
            Bs[(c4 + 2) * MLDS + kk] = f2tf32(v.z);
            Bs[(c4 + 3) * MLDS + kk] = f2tf32(v.w);
        }
        __syncthreads();
#pragma unroll
        for (int ks = 0; ks < 4; ks++) {
            uint32_t a[2][4], b[2][4];
#pragma unroll
            for (int mt = 0; mt < 2; mt++)
                ldsm4(a[mt][0], a[mt][1], a[mt][2], a[mt][3],
                      a_base + ((mt * 16 * MLDS + ks * 8) << 2));
#pragma unroll
            for (int p = 0; p < 2; p++)
                ldsm4(b[p][0], b[p][1], b[p][2], b[p][3],
                      b_base + ((p * 16 * MLDS + ks * 8) << 2));
#pragma unroll
            for (int mt = 0; mt < 2; mt++)
#pragma unroll
                for (int nt = 0; nt < 4; nt++) {
                    int p = nt >> 1, s = (nt & 1) * 2;
                    mma_tf32(acc[mt][nt], a[mt], b[p][s], b[p][s + 1]);
                }
        }
        __syncthreads();
    }

    float* pm = gMscr + (size_t)blockIdx.z * (2048 * 256);
#pragma unroll
    for (int mt = 0; mt < 2; mt++) {
        int r0 = bm + wm * 32 + mt * 16 + (lane >> 2);
#pragma unroll
        for (int nt = 0; nt < 4; nt++) {
            int c0 = bn + wn * 32 + nt * 8 + (lane & 3) * 2;
            *(float2*)(pm + (size_t)r0 * 256 + c0) =
                make_float2(acc[mt][nt][0], acc[mt][nt][1]);
            *(float2*)(pm + (size_t)(r0 + 8) * 256 + c0) =
                make_float2(acc[mt][nt][2], acc[mt][nt][3]);
        }
    }
}

__global__ __launch_bounds__(256) void k_matred() {
    int i = (blockIdx.x * 256 + threadIdx.x) * 4;
    float4 s = *(const float4*)(gMscr + i);
#pragma unroll
    for (int kc = 1; kc < 4; kc++) {
        float4 v = *(const float4*)(gMscr + (size_t)kc * (2048 * 256) + i);
        s.x += v.x; s.y += v.y; s.z += v.z; s.w += v.w;
    }
    *(__half2*)(gMh + i)     = __floats2half2_rn(s.x, s.y);
    *(__half2*)(gMh + i + 2) = __floats2half2_rn(s.z, s.w);
}

__global__ __launch_bounds__(256) void k_cvtWk(const float* __restrict__ Wk) {
    int i = (blockIdx.x * 256 + threadIdx.x) * 4;
    float4 v = *(const float4*)(Wk + i);
    *(__half2*)(gWkh + i)     = __floats2half2_rn(v.x, v.y);
    *(__half2*)(gWkh + i + 2) = __floats2half2_rn(v.z, v.w);
}

// =====================================================================
// Kernel 1: hash-gather + dilated causal depthwise conv + LN + SiLU -> gEh
//   se tile in fp16: static smem 48 -> 28 KB => 8 blocks/SM, ~2x occupancy.
// =====================================================================
__global__ __launch_bounds__(256) void k_embed(const int* __restrict__ hashes,
                                               const int* __restrict__ offs,
                                               const float* __restrict__ emb,
                                               const float* __restrict__ cw,
                                               const float* __restrict__ lg,
                                               const float* __restrict__ lb) {
    const int TB = 32, HALO = PADL;
    __shared__ __half se[(TB + HALO) * ED];    // 21 KB
    __shared__ float swt[KW * ED];
    __shared__ float sg[ED], sb[ED];

    int tid = threadIdx.x;
    int b = blockIdx.y, t0 = blockIdx.x * TB;

    sg[tid] = lg[tid];
    sb[tid] = lb[tid];
#pragma unroll
    for (int k = 0; k < KW; k++) swt[k * ED + tid] = cw[tid * KW + k];

    int h = tid >> 5, d = tid & 31;
    int off_h = offs[h];
    for (int lt = 0; lt < TB + HALO; lt++) {
        int t = t0 - HALO + lt;
        float v = 0.f;
        if (t >= 0) {
            int row = hashes[(b * TT + t) * NH + h] + off_h;
            v = emb[(size_t)row * HD + d];
        }
        se[lt * ED + tid] = __float2half_rn(v);
    }
    __syncthreads();

    int wid = tid >> 5, lane = tid & 31;
    for (int it = 0; it < TB / 8; it++) {
        int tok = it * 8 + wid;
        int lt = tok + HALO;
        float c[8], ev[8];
        float s = 0.f, q = 0.f;
#pragma unroll
        for (int j = 0; j < 8; j++) {
            int ch = lane + 32 * j;
            float a = 0.f;
#pragma unroll
            for (int k = 0; k < KW; k++)
                a += __half2float(se[(lt - PADL + k * DILN) * ED + ch]) * swt[k * ED + ch];
            c[j] = a;
            ev[j] = __half2float(se[lt * ED + ch]);
            s += a; q += a * a;
        }
#pragma unroll
        for (int o = 16; o; o >>= 1) {
            s += __shfl_xor_sync(0xffffffffu, s, o);
            q += __shfl_xor_sync(0xffffffffu, q, o);
        }
        float mean = s * (1.f / ED);
        float var  = q * (1.f / ED) - mean * mean;
        float rstd = rsqrtf(var + 1e-5f);
#pragma unroll
        for (int j = 0; j < 8; j++) {
            int ch = lane + 32 * j;
            float y = (c[j] - mean) * rstd * sg[ch] + sb[ch];
            float o = ev[j] + y * (1.f / (1.f + expf(-y)));
            gEh[(size_t)(b * TT + t0 + tok) * ED + ch] = __float2half_rn(o);
        }
    }
}

// =====================================================================
// Kernel 3/5: fp16 tensor GEMM NT (m16n8k16), 128x128 block.
//   MODE 0: B = gWkh; epilogue -> 9 raw gate partials. MODE 1: B = gMh, scaled store.
// =====================================================================
#define LDSH 72
#define HBUF (128 * LDSH)                // halfs per operand buffer
#define GSM  (4 * HBUF * 2)              // 73728 B

template <int MODE>
__global__ __launch_bounds__(256, 2) void k_gemm(float* __restrict__ Cout,
                                                 const float* __restrict__ x,
                                                 const float* __restrict__ lkg,
                                                 const float* __restrict__ lkb,
                                                 const float* __restrict__ lqg,
                                                 const float* __restrict__ lqb) {
    extern __shared__ __half sh[];
    __half* As = sh;                     // [2][HBUF]
    __half* Bs = sh + 2 * HBUF;          // [2][HBUF]

    const __half* A  = gEh;
    const __half* Bp = (MODE == 0) ? gWkh : gMh;

    int bm = blockIdx.y * 128, bn = blockIdx.x * 128;
    int tid = threadIdx.x, lane = tid & 31, wid = tid >> 5;
    int wm = wid & 1, wn = wid >> 1;

    float acc[4][4][4];
#pragma unroll
    for (int mt = 0; mt < 4; mt++)
#pragma unroll
        for (int nt = 0; nt < 4; nt++)
#pragma unroll
            for (int r = 0; r < 4; r++) acc[mt][nt][r] = 0.f;

    uint32_t as0 = smem_u32(As), bs0 = smem_u32(Bs);
    uint32_t a_base = as0 + (((wm * 64 + (lane & 15)) * LDSH + (lane >> 4) * 8) << 1);
    uint32_t b_base = bs0 + (((wn * 32 + (lane >> 4) * 8 + (lane & 7)) * LDSH
                              + ((lane >> 3) & 1) * 8) << 1);

    auto issue = [&](int t) {
        int s = t & 1;
        uint32_t ao = as0 + s * (HBUF * 2);
        uint32_t bo = bs0 + s * (HBUF * 2);
        int kt = t * 64;
#pragma unroll
        for (int i = 0; i < 4; i++) {
            int idx = tid + 256 * i;
            int row = idx >> 3, q = idx & 7;
            cpa16(ao + ((row * LDSH + q * 8) << 1), A  + (size_t)(bm + row) * ED + kt + q * 8);
            cpa16(bo + ((row * LDSH + q * 8) << 1), Bp + (size_t)(bn + row) * ED + kt + q * 8);
        }
        cpa_commit();
    };

    issue(0);
    for (int t = 0; t < 4; t++) {
        int s = t & 1;
        if (t < 3) { issue(t + 1); cpa_wait<1>(); }
        else       { cpa_wait<0>(); }
        __syncthreads();
        uint32_t abuf = a_base + s * (HBUF * 2);
        uint32_t bbuf = b_base + s * (HBUF * 2);
#pragma unroll
        for (int ks = 0; ks < 4; ks++) {
            uint32_t a[4][4], b[2][4];
#pragma unroll
            for (int mt = 0; mt < 4; mt++)
                ldsm4(a[mt][0], a[mt][1], a[mt][2], a[mt][3],
                      abuf + ((mt * 16 * LDSH + ks * 16) << 1));
#pragma unroll
            for (int p = 0; p < 2; p++)
                ldsm4(b[p][0], b[p][1], b[p][2], b[p][3],
                      bbuf + ((p * 16 * LDSH + ks * 16) << 1));
#pragma unroll
            for (int mt = 0; mt < 4; mt++)
#pragma unroll
                for (int nt = 0; nt < 4; nt++) {
                    int p = nt >> 1, q = (nt & 1) * 2;
                    mma_f16(acc[mt][nt], a[mt], b[p][q], b[p][q + 1]);
                }
        }
        __syncthreads();
    }

    if (MODE == 1) {
#pragma unroll
        for (int mt = 0; mt < 4; mt++) {
            int r0 = bm + wm * 64 + mt * 16 + (lane >> 2);
            float s0 = gG[r0], s1 = gG[r0 + 8];
#pragma unroll
            for (int nt = 0; nt < 4; nt++) {
                int c0 = bn + wn * 32 + nt * 8 + (lane & 3) * 2;
                *(float2*)(Cout + (size_t)r0 * HID + c0) =
                    make_float2(acc[mt][nt][0] * s0, acc[mt][nt][1] * s0);
                *(float2*)(Cout + (size_t)(r0 + 8) * HID + c0) =
                    make_float2(acc[mt][nt][2] * s1, acc[mt][nt][3] * s1);
            }
        }
    } else {
        // 9 raw partials: P0=Σkp·a·x P1=Σkp·a P2=Σa·x P3=Σkp·b P4=Σc·x
        //                 P5=Σkp P6=Σkp² P7=Σx P8=Σx²  (a=lkg·lqg, b=lkg·lqb, c=lkb·lqg)
        float* sA   = (float*)sh;        // [128] per-col a
        float* sB   = sA + 128;          // [128]
        float* sC   = sB + 128;          // [128]
        float* sRed = sC + 128;          // [4][128][9]
        if (tid < 128) {
            int col = bn + tid;
            float g1 = lkg[col], q1 = lqg[col], b1 = lkb[col], q0 = lqb[col];
            sA[tid] = g1 * q1; sB[tid] = g1 * q0; sC[tid] = b1 * q1;
        }
        __syncthreads();
#pragma unroll
        for (int mt = 0; mt < 4; mt++) {
#pragma unroll
            for (int half = 0; half < 2; half++) {
                int rl = wm * 64 + mt * 16 + half * 8 + (lane >> 2);
                int row = bm + rl;
                float p[9];
#pragma unroll
                for (int j = 0; j < 9; j++) p[j] = 0.f;
#pragma unroll
                for (int nt = 0; nt < 4; nt++) {
#pragma unroll
                    for (int e = 0; e < 2; e++) {
                        int cl = wn * 32 + nt * 8 + (lane & 3) * 2 + e;
                        float kp = acc[mt][nt][half * 2 + e];
                        float xv = x[(size_t)row * HID + bn + cl];
                        float a = sA[cl], b = sB[cl], c = sC[cl];
                        float ax = a * xv;
                        p[0] += kp * ax;
                        p[1] += kp * a;
                        p[2] += ax;
                        p[3] += kp * b;
                        p[4] += c * xv;
                        p[5] += kp;
                        p[6] += kp * kp;
                        p[7] += xv;
                        p[8] += xv * xv;
                    }
                }
#pragma unroll
                for (int o = 1; o <= 2; o <<= 1)
#pragma unroll
                    for (int j = 0; j < 9; j++)
                        p[j] += __shfl_xor_sync(0xffffffffu, p[j], o);
                if ((lane & 3) == 0) {
                    float* d = sRed + ((size_t)wn * 128 + rl) * 9;
#pragma unroll
                    for (int j = 0; j < 9; j++) d[j] = p[j];
                }
            }
        }
        __syncthreads();
        for (int idx = tid; idx < 128 * 9; idx += 256) {
            int rl = idx / 9, j = idx - rl * 9;
            float s = sRed[((size_t)0 * 128 + rl) * 9 + j]
                    + sRed[((size_t)1 * 128 + rl) * 9 + j]
                    + sRed[((size_t)2 * 128 + rl) * 9 + j]
                    + sRed[((size_t)3 * 128 + rl) * 9 + j];
            gPart[(((size_t)(bm + rl)) * 16 + blockIdx.x) * 16 + j] = s;
        }
    }
}

// =====================================================================
// Kernel 4: finalize gate (LN-weight constants computed in-block)
// =====================================================================
__global__ __launch_bounds__(256) void k_gfin(const float* __restrict__ lkg,
                                              const float* __restrict__ lkb,
                                              const float* __restrict__ lqg,
                                              const float* __restrict__ lqb) {
    __shared__ float cred[4][8];
    __shared__ float4 Cs;
    int tid = threadIdx.x, lane = tid & 31, wid = tid >> 5;

    float sa = 0.f, sb = 0.f, sc = 0.f, sd = 0.f;
    for (int c = tid; c < HID; c += 256) {
        float g1 = lkg[c], b1 = lkb[c], q1 = lqg[c], q0 = lqb[c];
        sa += g1 * q1; sb += g1 * q0; sc += b1 * q1; sd += b1 * q0;
    }
#pragma unroll
    for (int o = 16; o; o >>= 1) {
        sa += __shfl_xor_sync(0xffffffffu, sa, o);
        sb += __shfl_xor_sync(0xffffffffu, sb, o);
        sc += __shfl_xor_sync(0xffffffffu, sc, o);
        sd += __shfl_xor_sync(0xffffffffu, sd, o);
    }
    if (lane == 0) { cred[0][wid] = sa; cred[1][wid] = sb; cred[2][wid] = sc; cred[3][wid] = sd; }
    __syncthreads();
    if (tid == 0) {
        float a = 0.f, b = 0.f, c = 0.f, d = 0.f;
#pragma unroll
        for (int w = 0; w < 8; w++) { a += cred[0][w]; b += cred[1][w]; c += cred[2][w]; d += cred[3][w]; }
        Cs = make_float4(a, b, c, d);
    }
    __syncthreads();
    float4 C = Cs;

    int row = blockIdx.x * 256 + tid;
    float P[9];
#pragma unroll
    for (int j = 0; j < 9; j++) P[j] = 0.f;
#pragma unroll
    for (int nb = 0; nb < 16; nb++) {
        const float* p = gPart + (((size_t)row) * 16 + nb) * 16;
#pragma unroll
        for (int j = 0; j < 9; j++) P[j] += p[j];
    }
    float mk = P[5] * (1.f / HID);
    float rk = rsqrtf(P[6] * (1.f / HID) - mk * mk + 1e-5f);
    float mx = P[7] * (1.f / HID);
    float rx = rsqrtf(P[8] * (1.f / HID) - mx * mx + 1e-5f);
    float dot = rk * rx * (P[0] - mx * P[1] - mk * P[2] + mk * mx * C.x)
              + rk * (P[3] - mk * C.y)
              + rx * (P[4] - mx * C.z)
              + C.w;
    float s = dot * rsqrtf((float)HID);
    float a = fmaxf(fabsf(s), 1e-6f);
    float sgn = (s > 0.f) ? 1.f : ((s < 0.f) ? -1.f : 0.f);
    gG[row] = 1.f / (1.f + expf(-sqrtf(a) * sgn));
}

// =====================================================================
extern "C" void kernel_launch(void* const* d_in, const int* in_sizes, int n_in,
                              void* d_out, int out_size) {
    const float* x      = (const float*)d_in[0];
    const int*   hashes = (const int*)  d_in[1];
    const int*   offs   = (const int*)  d_in[2];
    const float* emb    = (const float*)d_in[3];
    const float* convw  = (const float*)d_in[4];
    const float* lncg   = (const float*)d_in[5];
    const float* lncb   = (const float*)d_in[6];
    const float* Wk     = (const float*)d_in[7];
    const float* Wv     = (const float*)d_in[8];
    const float* Wo     = (const float*)d_in[9];
    const float* lkg    = (const float*)d_in[10];
    const float* lkb    = (const float*)d_in[11];
    const float* lqg    = (const float*)d_in[12];
    const float* lqb    = (const float*)d_in[13];
    float* out = (float*)d_out;

    cudaFuncSetAttribute(k_gemm<0>, cudaFuncAttributeMaxDynamicSharedMemorySize, GSM);
    cudaFuncSetAttribute(k_gemm<1>, cudaFuncAttributeMaxDynamicSharedMemorySize, GSM);

    // Lazily created stream/events (resource setup only; per-call work identical).
    static cudaStream_t sideS = nullptr;
    static cudaEvent_t evFork = nullptr, evJoin = nullptr;
    if (sideS == nullptr) {
        cudaStreamCreateWithFlags(&sideS, cudaStreamNonBlocking);
        cudaEventCreateWithFlags(&evFork, cudaEventDisableTiming);
        cudaEventCreateWithFlags(&evJoin, cudaEventDisableTiming);
    }

    // ---- side stream: M = Wo @ Wv (only needed by the LAST gemm) ----
    cudaEventRecord(evFork, 0);
    cudaStreamWaitEvent(sideS, evFork, 0);
    k_matM5<<<dim3(4, 16, 4), 256, 0, sideS>>>(Wo, Wv);
    k_matred<<<512, 256, 0, sideS>>>();
    cudaEventRecord(evJoin, sideS);

    // ---- main stream ----
    k_cvtWk<<<HID * ED / 1024, 256>>>(Wk);
    k_embed<<<dim3(TT / 32, BB), 256>>>(hashes, offs, emb, convw, lncg, lncb);
    k_gemm<0><<<dim3(HID / 128, BT / 128), 256, GSM>>>(nullptr, x, lkg, lkb, lqg, lqb);
    k_gfin<<<BT / 256, 256>>>(lkg, lkb, lqg, lqb);

    cudaStreamWaitEvent(0, evJoin, 0);   // join matM chain before the value GEMM
    k_gemm<1><<<dim3(HID / 128, BT / 128), 256, GSM>>>(out, x, lkg, lkb, lqg, lqb);
}

// round 16
// speedup vs baseline: 1.1273x; 1.0581x over previous
#include <cuda_runtime.h>
#include <cuda_fp16.h>
#include <math.h>
#include <stdint.h>

// ---------------- problem constants ----------------
#define BB   4
#define TT   4096
#define BT   (BB*TT)      // 16384 tokens
#define HID  2048
#define ED   256          // engram dim
#define NH   8            // total hash heads
#define HD   32           // head dim
#define KW   4            // conv kernel
#define DILN 3            // dilation
#define PADL 9            // causal left pad

// ---------------- scratch (device globals; no allocation) ----------------
__device__ __align__(16) __half gEh [(size_t)BT * ED];      // e' fp16 (8 MB)
__device__ __align__(16) __half gMh [(size_t)HID * ED];     // M = Wo@Wv fp16 (1 MB)
__device__ __align__(16) __half gWkh[(size_t)HID * ED];     // Wk fp16 (1 MB)
__device__ float gG[BT];                                    // per-token gate
__device__ __align__(16) float gPart[(size_t)BT * 16 * 16]; // gate partials (16 MB)
__device__ __align__(16) float gMscr[(size_t)4 * HID * ED]; // matM split-K scratch (8 MB)

// ---------------- helpers ----------------------------------------------
__device__ __forceinline__ uint32_t f2tf32(float f) {
    uint32_t u; asm("cvt.rna.tf32.f32 %0, %1;" : "=r"(u) : "f"(f)); return u;
}
__device__ __forceinline__ uint32_t smem_u32(const void* p) {
    uint32_t r;
    asm("{ .reg .u64 t; cvta.to.shared.u64 t, %1; cvt.u32.u64 %0, t; }" : "=r"(r) : "l"(p));
    return r;
}
__device__ __forceinline__ void ldsm4(uint32_t& r0, uint32_t& r1, uint32_t& r2, uint32_t& r3,
                                      uint32_t addr) {
    asm volatile("ldmatrix.sync.aligned.m8n8.x4.shared.b16 {%0,%1,%2,%3}, [%4];"
                 : "=r"(r0), "=r"(r1), "=r"(r2), "=r"(r3) : "r"(addr));
}
__device__ __forceinline__ void mma_f16(float* c, const uint32_t* a, uint32_t b0, uint32_t b1) {
    asm volatile("mma.sync.aligned.m16n8k16.row.col.f32.f16.f16.f32 "
                 "{%0,%1,%2,%3}, {%4,%5,%6,%7}, {%8,%9}, {%0,%1,%2,%3};"
                 : "+f"(c[0]), "+f"(c[1]), "+f"(c[2]), "+f"(c[3])
                 : "r"(a[0]), "r"(a[1]), "r"(a[2]), "r"(a[3]), "r"(b0), "r"(b1));
}
__device__ __forceinline__ void mma_tf32(float* c, const uint32_t* a, uint32_t b0, uint32_t b1) {
    asm volatile("mma.sync.aligned.m16n8k8.row.col.f32.tf32.tf32.f32 "
                 "{%0,%1,%2,%3}, {%4,%5,%6,%7}, {%8,%9}, {%0,%1,%2,%3};"
                 : "+f"(c[0]), "+f"(c[1]), "+f"(c[2]), "+f"(c[3])
                 : "r"(a[0]), "r"(a[1]), "r"(a[2]), "r"(a[3]), "r"(b0), "r"(b1));
}
__device__ __forceinline__ void cpa16(uint32_t dst, const void* src) {
    asm volatile("cp.async.ca.shared.global [%0], [%1], 16;" :: "r"(dst), "l"(src));
}
__device__ __forceinline__ void cpa_commit() { asm volatile("cp.async.commit_group;"); }
template <int N> __device__ __forceinline__ void cpa_wait() {
    asm volatile("cp.async.wait_group %0;" :: "n"(N) : "memory");
}

// =====================================================================
// Kernel 0: matM split-K (tf32 tensor cores) -> gMscr
// =====================================================================
#define MLDS 36
__global__ __launch_bounds__(256) void k_matM5(const float* __restrict__ Wo,
                                               const float* __restrict__ Wv) {
    __shared__ uint32_t As[128 * MLDS];
    __shared__ uint32_t Bs[64 * MLDS];
    int bn = blockIdx.x * 64;
    int bm = blockIdx.y * 128;
    int K0 = blockIdx.z * 512;
    int tid = threadIdx.x, lane = tid & 31, wid = tid >> 5;
    int wm = wid & 3, wn = wid >> 2;

    float acc[2][4][4];
#pragma unroll
    for (int mt = 0; mt < 2; mt++)
#pragma unroll
        for (int nt = 0; nt < 4; nt++)
#pragma unroll
            for (int r = 0; r < 4; r++) acc[mt][nt][r] = 0.f;

    uint32_t as0 = smem_u32(As), bs0 = smem_u32(Bs);
    uint32_t a_base = as0 + (((wm * 32 + (lane & 15)) * MLDS + (lane >> 4) * 4) << 2);
    uint32_t b_base = bs0 + (((wn * 32 + (lane >> 4) * 8 + (lane & 7)) * MLDS
                              + ((lane >> 3) & 1) * 4) << 2);

    for (int kt = 0; kt < 512; kt += 32) {
#pragma unroll
        for (int i = 0; i < 4; i++) {
            int idx = tid + 256 * i;
            int r = idx >> 3, q = idx & 7;
            float4 v = *(const float4*)(Wo + (size_t)(bm + r) * 2048 + K0 + kt + q * 4);
            uint32_t* d = &As[r * MLDS + q * 4];
            d[0] = f2tf32(v.x); d[1] = f2tf32(v.y); d[2] = f2tf32(v.z); d[3] = f2tf32(v.w);
        }
#pragma unroll
        for (int p = 0; p < 2; p++) {
            int kk = (tid >> 4) + p * 16;
            int c4 = (tid & 15) * 4;
            float4 v = *(const float4*)(Wv + (size_t)(K0 + kt + kk) * 256 + bn + c4);
            Bs[(c4 + 0) * MLDS + kk] = f2tf32(v.x);
            Bs[(c4 + 1) * MLDS + kk] = f2tf32(v.y);
            Bs[(c4 + 2) * MLDS + kk] = f2tf32(v.z);
            Bs[(c4 + 3) * MLDS + kk] = f2tf32(v.w);
        }
        __syncthreads();
#pragma unroll
        for (int ks = 0; ks < 4; ks++) {
            uint32_t a[2][4], b[2][4];
#pragma unroll
            for (int mt = 0; mt < 2; mt++)
                ldsm4(a[mt][0], a[mt][1], a[mt][2], a[mt][3],
                      a_base + ((mt * 16 * MLDS + ks * 8) << 2));
#pragma unroll
            for (int p = 0; p < 2; p++)
                ldsm4(b[p][0], b[p][1], b[p][2], b[p][3],
                      b_base + ((p * 16 * MLDS + ks * 8) << 2));
#pragma unroll
            for (int mt = 0; mt < 2; mt++)
#pragma unroll
                for (int nt = 0; nt < 4; nt++) {
                    int p = nt >> 1, s = (nt & 1) * 2;
                    mma_tf32(acc[mt][nt], a[mt], b[p][s], b[p][s + 1]);
                }
        }
        __syncthreads();
    }

    float* pm = gMscr + (size_t)blockIdx.z * (2048 * 256);
#pragma unroll
    for (int mt = 0; mt < 2; mt++) {
        int r0 = bm + wm * 32 + mt * 16 + (lane >> 2);
#pragma unroll
        for (int nt = 0; nt < 4; nt++) {
            int c0 = bn + wn * 32 + nt * 8 + (lane & 3) * 2;
            *(float2*)(pm + (size_t)r0 * 256 + c0) =
                make_float2(acc[mt][nt][0], acc[mt][nt][1]);
            *(float2*)(pm + (size_t)(r0 + 8) * 256 + c0) =
                make_float2(acc[mt][nt][2], acc[mt][nt][3]);
        }
    }
}

__global__ __launch_bounds__(256) void k_matred() {
    int i = (blockIdx.x * 256 + threadIdx.x) * 4;
    float4 s = *(const float4*)(gMscr + i);
#pragma unroll
    for (int kc = 1; kc < 4; kc++) {
        float4 v = *(const float4*)(gMscr + (size_t)kc * (2048 * 256) + i);
        s.x += v.x; s.y += v.y; s.z += v.z; s.w += v.w;
    }
    *(__half2*)(gMh + i)     = __floats2half2_rn(s.x, s.y);
    *(__half2*)(gMh + i + 2) = __floats2half2_rn(s.z, s.w);
}

__global__ __launch_bounds__(256) void k_cvtWk(const float* __restrict__ Wk) {
    int i = (blockIdx.x * 256 + threadIdx.x) * 4;
    float4 v = *(const float4*)(Wk + i);
    *(__half2*)(gWkh + i)     = __floats2half2_rn(v.x, v.y);
    *(__half2*)(gWkh + i + 2) = __floats2half2_rn(v.z, v.w);
}

// =====================================================================
// Kernel 1: hash-gather + dilated causal depthwise conv + LN + SiLU -> gEh
//   __launch_bounds__(256, 6): cap regs (~42) so 6 blocks/SM fit (occ ~75%).
// =====================================================================
__global__ __launch_bounds__(256, 6) void k_embed(const int* __restrict__ hashes,
                                                  const int* __restrict__ offs,
                                                  const float* __restrict__ emb,
                                                  const float* __restrict__ cw,
                                                  const float* __restrict__ lg,
                                                  const float* __restrict__ lb) {
    const int TB = 32, HALO = PADL;
    __shared__ __half se[(TB + HALO) * ED];    // 21 KB
    __shared__ float swt[KW * ED];
    __shared__ float sg[ED], sb[ED];

    int tid = threadIdx.x;
    int b = blockIdx.y, t0 = blockIdx.x * TB;

    sg[tid] = lg[tid];
    sb[tid] = lb[tid];
#pragma unroll
    for (int k = 0; k < KW; k++) swt[k * ED + tid] = cw[tid * KW + k];

    int h = tid >> 5, d = tid & 31;
    int off_h = offs[h];
    for (int lt = 0; lt < TB + HALO; lt++) {
        int t = t0 - HALO + lt;
        float v = 0.f;
        if (t >= 0) {
            int row = hashes[(b * TT + t) * NH + h] + off_h;
            v = emb[(size_t)row * HD + d];
        }
        se[lt * ED + tid] = __float2half_rn(v);
    }
    __syncthreads();

    int wid = tid >> 5, lane = tid & 31;
    for (int it = 0; it < TB / 8; it++) {
        int tok = it * 8 + wid;
        int lt = tok + HALO;
        float c[8], ev[8];
        float s = 0.f, q = 0.f;
#pragma unroll
        for (int j = 0; j < 8; j++) {
            int ch = lane + 32 * j;
            float a = 0.f;
#pragma unroll
            for (int k = 0; k < KW; k++)
                a += __half2float(se[(lt - PADL + k * DILN) * ED + ch]) * swt[k * ED + ch];
            c[j] = a;
            ev[j] = __half2float(se[lt * ED + ch]);
            s += a; q += a * a;
        }
#pragma unroll
        for (int o = 16; o; o >>= 1) {
            s += __shfl_xor_sync(0xffffffffu, s, o);
            q += __shfl_xor_sync(0xffffffffu, q, o);
        }
        float mean = s * (1.f / ED);
        float var  = q * (1.f / ED) - mean * mean;
        float rstd = rsqrtf(var + 1e-5f);
#pragma unroll
        for (int j = 0; j < 8; j++) {
            int ch = lane + 32 * j;
            float y = (c[j] - mean) * rstd * sg[ch] + sb[ch];
            float o = ev[j] + y * (1.f / (1.f + expf(-y)));
            gEh[(size_t)(b * TT + t0 + tok) * ED + ch] = __float2half_rn(o);
        }
    }
}

// =====================================================================
// Kernel 3/5: fp16 tensor GEMM NT (m16n8k16), 128x128 block.
//   MODE 0: B = gWkh; epilogue -> 9 raw gate partials. MODE 1: B = gMh, scaled store.
// =====================================================================
#define LDSH 72
#define HBUF (128 * LDSH)                // halfs per operand buffer
#define GSM  (4 * HBUF * 2)              // 73728 B

template <int MODE>
__global__ __launch_bounds__(256, 2) void k_gemm(float* __restrict__ Cout,
                                                 const float* __restrict__ x,
                                                 const float* __restrict__ lkg,
                                                 const float* __restrict__ lkb,
                                                 const float* __restrict__ lqg,
                                                 const float* __restrict__ lqb) {
    extern __shared__ __half sh[];
    __half* As = sh;                     // [2][HBUF]
    __half* Bs = sh + 2 * HBUF;          // [2][HBUF]

    const __half* A  = gEh;
    const __half* Bp = (MODE == 0) ? gWkh : gMh;

    int bm = blockIdx.y * 128, bn = blockIdx.x * 128;
    int tid = threadIdx.x, lane = tid & 31, wid = tid >> 5;
    int wm = wid & 1, wn = wid >> 1;

    float acc[4][4][4];
#pragma unroll
    for (int mt = 0; mt < 4; mt++)
#pragma unroll
        for (int nt = 0; nt < 4; nt++)
#pragma unroll
            for (int r = 0; r < 4; r++) acc[mt][nt][r] = 0.f;

    uint32_t as0 = smem_u32(As), bs0 = smem_u32(Bs);
    uint32_t a_base = as0 + (((wm * 64 + (lane & 15)) * LDSH + (lane >> 4) * 8) << 1);
    uint32_t b_base = bs0 + (((wn * 32 + (lane >> 4) * 8 + (lane & 7)) * LDSH
                              + ((lane >> 3) & 1) * 8) << 1);

    auto issue = [&](int t) {
        int s = t & 1;
        uint32_t ao = as0 + s * (HBUF * 2);
        uint32_t bo = bs0 + s * (HBUF * 2);
        int kt = t * 64;
#pragma unroll
        for (int i = 0; i < 4; i++) {
            int idx = tid + 256 * i;
            int row = idx >> 3, q = idx & 7;
            cpa16(ao + ((row * LDSH + q * 8) << 1), A  + (size_t)(bm + row) * ED + kt + q * 8);
            cpa16(bo + ((row * LDSH + q * 8) << 1), Bp + (size_t)(bn + row) * ED + kt + q * 8);
        }
        cpa_commit();
    };

    issue(0);
    for (int t = 0; t < 4; t++) {
        int s = t & 1;
        if (t < 3) { issue(t + 1); cpa_wait<1>(); }
        else       { cpa_wait<0>(); }
        __syncthreads();
        uint32_t abuf = a_base + s * (HBUF * 2);
        uint32_t bbuf = b_base + s * (HBUF * 2);
#pragma unroll
        for (int ks = 0; ks < 4; ks++) {
            uint32_t a[4][4], b[2][4];
#pragma unroll
            for (int mt = 0; mt < 4; mt++)
                ldsm4(a[mt][0], a[mt][1], a[mt][2], a[mt][3],
                      abuf + ((mt * 16 * LDSH + ks * 16) << 1));
#pragma unroll
            for (int p = 0; p < 2; p++)
                ldsm4(b[p][0], b[p][1], b[p][2], b[p][3],
                      bbuf + ((p * 16 * LDSH + ks * 16) << 1));
#pragma unroll
            for (int mt = 0; mt < 4; mt++)
#pragma unroll
                for (int nt = 0; nt < 4; nt++) {
                    int p = nt >> 1, q = (nt & 1) * 2;
                    mma_f16(acc[mt][nt], a[mt], b[p][q], b[p][q + 1]);
                }
        }
        __syncthreads();
    }

    if (MODE == 1) {
#pragma unroll
        for (int mt = 0; mt < 4; mt++) {
            int r0 = bm + wm * 64 + mt * 16 + (lane >> 2);
            float s0 = gG[r0], s1 = gG[r0 + 8];
#pragma unroll
            for (int nt = 0; nt < 4; nt++) {
                int c0 = bn + wn * 32 + nt * 8 + (lane & 3) * 2;
                *(float2*)(Cout + (size_t)r0 * HID + c0) =
                    make_float2(acc[mt][nt][0] * s0, acc[mt][nt][1] * s0);
                *(float2*)(Cout + (size_t)(r0 + 8) * HID + c0) =
                    make_float2(acc[mt][nt][2] * s1, acc[mt][nt][3] * s1);
            }
        }
    } else {
        // 9 raw partials: P0=Σkp·a·x P1=Σkp·a P2=Σa·x P3=Σkp·b P4=Σc·x
        //                 P5=Σkp P6=Σkp² P7=Σx P8=Σx²  (a=lkg·lqg, b=lkg·lqb, c=lkb·lqg)
        float* sA   = (float*)sh;        // [128] per-col a
        float* sB   = sA + 128;          // [128]
        float* sC   = sB + 128;          // [128]
        float* sRed = sC + 128;          // [4][128][9]
        if (tid < 128) {
            int col = bn + tid;
            float g1 = lkg[col], q1 = lqg[col], b1 = lkb[col], q0 = lqb[col];
            sA[tid] = g1 * q1; sB[tid] = g1 * q0; sC[tid] = b1 * q1;
        }
        __syncthreads();
#pragma unroll
        for (int mt = 0; mt < 4; mt++) {
#pragma unroll
            for (int half = 0; half < 2; half++) {
                int rl = wm * 64 + mt * 16 + half * 8 + (lane >> 2);
                int row = bm + rl;
                float p[9];
#pragma unroll
                for (int j = 0; j < 9; j++) p[j] = 0.f;
#pragma unroll
                for (int nt = 0; nt < 4; nt++) {
#pragma unroll
                    for (int e = 0; e < 2; e++) {
                        int cl = wn * 32 + nt * 8 + (lane & 3) * 2 + e;
                        float kp = acc[mt][nt][half * 2 + e];
                        float xv = x[(size_t)row * HID + bn + cl];
                        float a = sA[cl], b = sB[cl], c = sC[cl];
                        float ax = a * xv;
                        p[0] += kp * ax;
                        p[1] += kp * a;
                        p[2] += ax;
                        p[3] += kp * b;
                        p[4] += c * xv;
                        p[5] += kp;
                        p[6] += kp * kp;
                        p[7] += xv;
                        p[8] += xv * xv;
                    }
                }
#pragma unroll
                for (int o = 1; o <= 2; o <<= 1)
#pragma unroll
                    for (int j = 0; j < 9; j++)
                        p[j] += __shfl_xor_sync(0xffffffffu, p[j], o);
                if ((lane & 3) == 0) {
                    float* d = sRed + ((size_t)wn * 128 + rl) * 9;
#pragma unroll
                    for (int j = 0; j < 9; j++) d[j] = p[j];
                }
            }
        }
        __syncthreads();
        for (int idx = tid; idx < 128 * 9; idx += 256) {
            int rl = idx / 9, j = idx - rl * 9;
            float s = sRed[((size_t)0 * 128 + rl) * 9 + j]
                    + sRed[((size_t)1 * 128 + rl) * 9 + j]
                    + sRed[((size_t)2 * 128 + rl) * 9 + j]
                    + sRed[((size_t)3 * 128 + rl) * 9 + j];
            gPart[(((size_t)(bm + rl)) * 16 + blockIdx.x) * 16 + j] = s;
        }
    }
}

// =====================================================================
// Kernel 4: finalize gate (LN-weight constants computed in-block)
// =====================================================================
__global__ __launch_bounds__(256) void k_gfin(const float* __restrict__ lkg,
                                              const float* __restrict__ lkb,
                                              const float* __restrict__ lqg,
                                              const float* __restrict__ lqb) {
    __shared__ float cred[4][8];
    __shared__ float4 Cs;
    int tid = threadIdx.x, lane = tid & 31, wid = tid >> 5;

    float sa = 0.f, sb = 0.f, sc = 0.f, sd = 0.f;
    for (int c = tid; c < HID; c += 256) {
        float g1 = lkg[c], b1 = lkb[c], q1 = lqg[c], q0 = lqb[c];
        sa += g1 * q1; sb += g1 * q0; sc += b1 * q1; sd += b1 * q0;
    }
#pragma unroll
    for (int o = 16; o; o >>= 1) {
        sa += __shfl_xor_sync(0xffffffffu, sa, o);
        sb += __shfl_xor_sync(0xffffffffu, sb, o);
        sc += __shfl_xor_sync(0xffffffffu, sc, o);
        sd += __shfl_xor_sync(0xffffffffu, sd, o);
    }
    if (lane == 0) { cred[0][wid] = sa; cred[1][wid] = sb; cred[2][wid] = sc; cred[3][wid] = sd; }
    __syncthreads();
    if (tid == 0) {
        float a = 0.f, b = 0.f, c = 0.f, d = 0.f;
#pragma unroll
        for (int w = 0; w < 8; w++) { a += cred[0][w]; b += cred[1][w]; c += cred[2][w]; d += cred[3][w]; }
        Cs = make_float4(a, b, c, d);
    }
    __syncthreads();
    float4 C = Cs;

    int row = blockIdx.x * 256 + tid;
    float P[9];
#pragma unroll
    for (int j = 0; j < 9; j++) P[j] = 0.f;
#pragma unroll
    for (int nb = 0; nb < 16; nb++) {
        const float* p = gPart + (((size_t)row) * 16 + nb) * 16;
#pragma unroll
        for (int j = 0; j < 9; j++) P[j] += p[j];
    }
    float mk = P[5] * (1.f / HID);
    float rk = rsqrtf(P[6] * (1.f / HID) - mk * mk + 1e-5f);
    float mx = P[7] * (1.f / HID);
    float rx = rsqrtf(P[8] * (1.f / HID) - mx * mx + 1e-5f);
    float dot = rk * rx * (P[0] - mx * P[1] - mk * P[2] + mk * mx * C.x)
              + rk * (P[3] - mk * C.y)
              + rx * (P[4] - mx * C.z)
              + C.w;
    float s = dot * rsqrtf((float)HID);
    float a = fmaxf(fabsf(s), 1e-6f);
    float sgn = (s > 0.f) ? 1.f : ((s < 0.f) ? -1.f : 0.f);
    gG[row] = 1.f / (1.f + expf(-sqrtf(a) * sgn));
}

// =====================================================================
extern "C" void kernel_launch(void* const* d_in, const int* in_sizes, int n_in,
                              void* d_out, int out_size) {
    const float* x      = (const float*)d_in[0];
    const int*   hashes = (const int*)  d_in[1];
    const int*   offs   = (const int*)  d_in[2];
    const float* emb    = (const float*)d_in[3];
    const float* convw  = (const float*)d_in[4];
    const float* lncg   = (const float*)d_in[5];
    const float* lncb   = (const float*)d_in[6];
    const float* Wk     = (const float*)d_in[7];
    const float* Wv     = (const float*)d_in[8];
    const float* Wo     = (const float*)d_in[9];
    const float* lkg    = (const float*)d_in[10];
    const float* lkb    = (const float*)d_in[11];
    const float* lqg    = (const float*)d_in[12];
    const float* lqb    = (const float*)d_in[13];
    float* out = (float*)d_out;

    cudaFuncSetAttribute(k_gemm<0>, cudaFuncAttributeMaxDynamicSharedMemorySize, GSM);
    cudaFuncSetAttribute(k_gemm<1>, cudaFuncAttributeMaxDynamicSharedMemorySize, GSM);

    // Lazily created stream/events (resource setup only; per-call work identical).
    static cudaStream_t sideS = nullptr;
    static cudaEvent_t evFork = nullptr, evWk = nullptr, evJoin = nullptr;
    if (sideS == nullptr) {
        cudaStreamCreateWithFlags(&sideS, cudaStreamNonBlocking);
        cudaEventCreateWithFlags(&evFork, cudaEventDisableTiming);
        cudaEventCreateWithFlags(&evWk,   cudaEventDisableTiming);
        cudaEventCreateWithFlags(&evJoin, cudaEventDisableTiming);
    }

    // ---- side stream: Wk convert, then M = Wo @ Wv ----
    cudaEventRecord(evFork, 0);
    cudaStreamWaitEvent(sideS, evFork, 0);
    k_cvtWk<<<HID * ED / 1024, 256, 0, sideS>>>(Wk);
    cudaEventRecord(evWk, sideS);                  // gemm0 needs gWkh
    k_matM5<<<dim3(4, 16, 4), 256, 0, sideS>>>(Wo, Wv);
    k_matred<<<512, 256, 0, sideS>>>();
    cudaEventRecord(evJoin, sideS);                // gemm1 needs gMh

    // ---- main stream ----
    k_embed<<<dim3(TT / 32, BB), 256>>>(hashes, offs, emb, convw, lncg, lncb);
    cudaStreamWaitEvent(0, evWk, 0);
    k_gemm<0><<<dim3(HID / 128, BT / 128), 256, GSM>>>(nullptr, x, lkg, lkb, lqg, lqb);
    k_gfin<<<BT / 256, 256>>>(lkg, lkb, lqg, lqb);

    cudaStreamWaitEvent(0, evJoin, 0);             // join matM chain before the value GEMM
    k_gemm<1><<<dim3(HID / 128, BT / 128), 256, GSM>>>(out, x, lkg, lkb, lqg, lqb);
}